// round 1
// baseline (speedup 1.0000x reference)
#include <cuda_runtime.h>

#define NB 4
#define NS 2048
#define NE 2048
#define NH 16
#define ND 128
#define NHDIM 2048              // NH*ND
#define CH (NB*NS*NHDIM)        // 16777216 elements per staged tensor

// scratch: [q | k | v | attn_out], 4 x 64MB fp32
__device__ float g_scratch[4ll * CH];

// ================================================================== GEMM (NT)
// C[m,n] = sum_k A[m,k] * W[n,k] (+ bias)
// A: [8192, 2048] row-major, W: [N, 2048] row-major (torch Linear weight)
#define BM 128
#define BN 128
#define BK 16
#define LDT 132                 // padded stride for transposed [BK][128] tiles

// mode == 1: fused QKV. A = x, W selected by blockIdx.x>>4, C = g_scratch[wsel],
//            output scattered to [B,H,S,D].
// mode == 0: proj. A = g_scratch + 3*CH (attn out, [m, NHDIM]), W = W0,
//            C = Cext row-major [m, NE] with bias.
__global__ __launch_bounds__(256, 2)
void gemm_nt(const float* __restrict__ Ax,
             const float* __restrict__ W0,
             const float* __restrict__ W1,
             const float* __restrict__ W2,
             const float* __restrict__ bias,
             float* __restrict__ Cext,
             int mode)
{
    __shared__ float As[BK][LDT];
    __shared__ float Bs[BK][LDT];

    const int tid = threadIdx.x;
    const int tx  = tid & 15;
    const int ty  = tid >> 4;

    int bx = blockIdx.x;
    const float* A = Ax;
    const float* W = W0;
    float* C = Cext;
    int wsel = 0;
    if (mode == 1) {
        wsel = bx >> 4;                 // 0,1,2 -> q,k,v
        bx &= 15;
        W = (wsel == 0) ? W0 : ((wsel == 1) ? W1 : W2);
        C = g_scratch + (size_t)wsel * CH;
    } else {
        A = g_scratch + 3ll * CH;       // attention output
    }

    const int m0 = blockIdx.y * BM;
    const int n0 = bx * BN;

    const float* Ag = A + (size_t)m0 * NE;
    const float* Wg = W + (size_t)n0 * NE;

    float acc[8][8];
    #pragma unroll
    for (int i = 0; i < 8; i++)
        #pragma unroll
        for (int j = 0; j < 8; j++)
            acc[i][j] = 0.0f;

    for (int k0 = 0; k0 < NE; k0 += BK) {
        // load A/B tiles (each 128x16 fp32 = 512 float4), transpose into [k][m]
        #pragma unroll
        for (int t = 0; t < 2; t++) {
            int row = (tid >> 2) + t * 64;   // 0..127
            int c4  = tid & 3;               // 0..3
            float4 va = *(const float4*)(Ag + (size_t)row * NE + k0 + c4 * 4);
            As[c4 * 4 + 0][row] = va.x;
            As[c4 * 4 + 1][row] = va.y;
            As[c4 * 4 + 2][row] = va.z;
            As[c4 * 4 + 3][row] = va.w;
            float4 vb = *(const float4*)(Wg + (size_t)row * NE + k0 + c4 * 4);
            Bs[c4 * 4 + 0][row] = vb.x;
            Bs[c4 * 4 + 1][row] = vb.y;
            Bs[c4 * 4 + 2][row] = vb.z;
            Bs[c4 * 4 + 3][row] = vb.w;
        }
        __syncthreads();

        #pragma unroll
        for (int kk = 0; kk < BK; kk++) {
            float a[8], b[8];
            *(float4*)&a[0] = *(const float4*)&As[kk][ty * 8];
            *(float4*)&a[4] = *(const float4*)&As[kk][ty * 8 + 4];
            *(float4*)&b[0] = *(const float4*)&Bs[kk][tx * 4];
            *(float4*)&b[4] = *(const float4*)&Bs[kk][64 + tx * 4];
            #pragma unroll
            for (int i = 0; i < 8; i++)
                #pragma unroll
                for (int j = 0; j < 8; j++)
                    acc[i][j] = fmaf(a[i], b[j], acc[i][j]);
        }
        __syncthreads();
    }

    if (mode == 1) {
        // scatter to [B,H,S,D]; whole block shares one head (BN == ND)
        const int h = n0 / ND;
        #pragma unroll
        for (int i = 0; i < 8; i++) {
            int m  = m0 + ty * 8 + i;
            int bb = m >> 11;               // / NS
            int s  = m & (NS - 1);
            float* dst = C + (((size_t)(bb * NH + h)) * NS + s) * ND;
            float4 v0 = make_float4(acc[i][0], acc[i][1], acc[i][2], acc[i][3]);
            float4 v1 = make_float4(acc[i][4], acc[i][5], acc[i][6], acc[i][7]);
            *(float4*)(dst + tx * 4)      = v0;
            *(float4*)(dst + 64 + tx * 4) = v1;
        }
    } else {
        float4 b0 = *(const float4*)(bias + n0 + tx * 4);
        float4 b1 = *(const float4*)(bias + n0 + 64 + tx * 4);
        #pragma unroll
        for (int i = 0; i < 8; i++) {
            int m = m0 + ty * 8 + i;
            float* dst = C + (size_t)m * NE + n0;
            float4 v0 = make_float4(acc[i][0] + b0.x, acc[i][1] + b0.y,
                                    acc[i][2] + b0.z, acc[i][3] + b0.w);
            float4 v1 = make_float4(acc[i][4] + b1.x, acc[i][5] + b1.y,
                                    acc[i][6] + b1.z, acc[i][7] + b1.w);
            *(float4*)(dst + tx * 4)      = v0;
            *(float4*)(dst + 64 + tx * 4) = v1;
        }
    }
}

// ============================================================ Flash attention
// per block: one (b,h) and one 64-row query tile; causal; online softmax.
#define BR 64
#define BC 64
#define QLD 68                  // stride for d-major Q/K and P^T tiles
#define VLD 132                 // stride for row-major V tile
#define FA_SMEM_FLOATS (2 * ND * QLD + BC * VLD + BC * QLD)
#define FA_SMEM_BYTES  (FA_SMEM_FLOATS * 4)   // 120832

__global__ __launch_bounds__(256)
void fattn()
{
    extern __shared__ float sm[];
    float* Qs = sm;                         // [d][row], stride QLD
    float* Ks = Qs + ND * QLD;              // [d][row], stride QLD
    float* Vs = Ks + ND * QLD;              // [j][c],  stride VLD
    float* Ps = Vs + BC * VLD;              // [j][i],  stride QLD (P transposed)

    const float* Qg = g_scratch;
    const float* Kg = g_scratch + (size_t)CH;
    const float* Vg = g_scratch + 2ll * CH;
    float*       Og = g_scratch + 3ll * CH;

    const int tid = threadIdx.x;
    const int tx  = tid & 15;
    const int ty  = tid >> 4;
    const int qs  = blockIdx.x * BR;
    const int bh  = blockIdx.y;             // b*NH + h

    const float* Qbase = Qg + (size_t)bh * NS * ND + (size_t)qs * ND;
    const float* Kbase = Kg + (size_t)bh * NS * ND;
    const float* Vbase = Vg + (size_t)bh * NS * ND;

    // load Q tile (64 x 128) transposed to d-major
    {
        int row = tid >> 2;                  // 0..63
        int cl  = tid & 3;
        #pragma unroll
        for (int t = 0; t < 8; t++) {
            int c4 = t * 4 + cl;             // 0..31
            float4 v = *(const float4*)(Qbase + (size_t)row * ND + c4 * 4);
            Qs[(c4 * 4 + 0) * QLD + row] = v.x;
            Qs[(c4 * 4 + 1) * QLD + row] = v.y;
            Qs[(c4 * 4 + 2) * QLD + row] = v.z;
            Qs[(c4 * 4 + 3) * QLD + row] = v.w;
        }
    }

    float m_i[4], l_i[4], oacc[4][8];
    #pragma unroll
    for (int i = 0; i < 4; i++) {
        m_i[i] = -1e30f;
        l_i[i] = 0.0f;
        #pragma unroll
        for (int c = 0; c < 8; c++) oacc[i][c] = 0.0f;
    }

    const float sc = 0.08838834764831845f;   // 1/sqrt(128)
    const int nkt = (qs >> 6) + 1;           // causal: key tiles 0..qs/64

    for (int kt = 0; kt < nkt; kt++) {
        const int ks = kt * BC;
        __syncthreads();                     // protect Ks/Vs/Ps reuse

        // K tile transposed to d-major
        {
            int row = tid >> 2;
            int cl  = tid & 3;
            const float* kb = Kbase + (size_t)(ks + row) * ND;
            #pragma unroll
            for (int t = 0; t < 8; t++) {
                int c4 = t * 4 + cl;
                float4 v = *(const float4*)(kb + c4 * 4);
                Ks[(c4 * 4 + 0) * QLD + row] = v.x;
                Ks[(c4 * 4 + 1) * QLD + row] = v.y;
                Ks[(c4 * 4 + 2) * QLD + row] = v.z;
                Ks[(c4 * 4 + 3) * QLD + row] = v.w;
            }
        }
        // V tile row-major
        {
            int vrow = tid >> 5;             // 0..7
            int vc   = tid & 31;
            #pragma unroll
            for (int t = 0; t < 8; t++) {
                int r = vrow + t * 8;
                float4 v = *(const float4*)(Vbase + (size_t)(ks + r) * ND + vc * 4);
                *(float4*)&Vs[r * VLD + vc * 4] = v;
            }
        }
        __syncthreads();

        // S = Q K^T  (each thread: rows ty*4.., cols tx*4..)
        float s[4][4];
        #pragma unroll
        for (int i = 0; i < 4; i++)
            #pragma unroll
            for (int j = 0; j < 4; j++) s[i][j] = 0.0f;

        #pragma unroll 4
        for (int d = 0; d < ND; d++) {
            float qv[4], kv[4];
            *(float4*)qv = *(const float4*)&Qs[d * QLD + ty * 4];
            *(float4*)kv = *(const float4*)&Ks[d * QLD + tx * 4];
            #pragma unroll
            for (int i = 0; i < 4; i++)
                #pragma unroll
                for (int j = 0; j < 4; j++)
                    s[i][j] = fmaf(qv[i], kv[j], s[i][j]);
        }

        // scale + causal mask (only diagonal tile overlaps)
        const bool diag = (ks == qs);
        float z[4][4];
        #pragma unroll
        for (int i = 0; i < 4; i++)
            #pragma unroll
            for (int j = 0; j < 4; j++) {
                float val = s[i][j] * sc;
                if (diag && (tx * 4 + j) > (ty * 4 + i)) val = -1e30f;
                z[i][j] = val;
            }

        // row max over this tile: local then butterfly across the 16 tx lanes
        float mt[4];
        #pragma unroll
        for (int i = 0; i < 4; i++)
            mt[i] = fmaxf(fmaxf(z[i][0], z[i][1]), fmaxf(z[i][2], z[i][3]));
        #pragma unroll
        for (int off = 8; off > 0; off >>= 1)
            #pragma unroll
            for (int i = 0; i < 4; i++)
                mt[i] = fmaxf(mt[i], __shfl_xor_sync(0xFFFFFFFFu, mt[i], off));

        float alpha[4], rs[4], p[4][4];
        #pragma unroll
        for (int i = 0; i < 4; i++) {
            float mn = fmaxf(m_i[i], mt[i]);
            alpha[i] = __expf(m_i[i] - mn);
            m_i[i] = mn;
            rs[i] = 0.0f;
            #pragma unroll
            for (int j = 0; j < 4; j++) {
                p[i][j] = __expf(z[i][j] - mn);   // masked -> exactly 0
                rs[i] += p[i][j];
            }
        }
        #pragma unroll
        for (int off = 8; off > 0; off >>= 1)
            #pragma unroll
            for (int i = 0; i < 4; i++)
                rs[i] += __shfl_xor_sync(0xFFFFFFFFu, rs[i], off);

        #pragma unroll
        for (int i = 0; i < 4; i++) {
            l_i[i] = l_i[i] * alpha[i] + rs[i];
            #pragma unroll
            for (int c = 0; c < 8; c++) oacc[i][c] *= alpha[i];
        }

        // stash P transposed for the PV gemm
        #pragma unroll
        for (int i = 0; i < 4; i++)
            #pragma unroll
            for (int j = 0; j < 4; j++)
                Ps[(tx * 4 + j) * QLD + (ty * 4 + i)] = p[i][j];
        __syncthreads();

        // O += P V   (cols tx*4.. and 64+tx*4..)
        #pragma unroll 4
        for (int j = 0; j < BC; j++) {
            float pv[4], vv[8];
            *(float4*)pv     = *(const float4*)&Ps[j * QLD + ty * 4];
            *(float4*)&vv[0] = *(const float4*)&Vs[j * VLD + tx * 4];
            *(float4*)&vv[4] = *(const float4*)&Vs[j * VLD + 64 + tx * 4];
            #pragma unroll
            for (int i = 0; i < 4; i++)
                #pragma unroll
                for (int c = 0; c < 8; c++)
                    oacc[i][c] = fmaf(pv[i], vv[c], oacc[i][c]);
        }
    }

    // write O in [b, s, h, d] so the proj GEMM reads it row-major [m, NHDIM]
    const int b = bh >> 4;
    const int h = bh & 15;
    #pragma unroll
    for (int i = 0; i < 4; i++) {
        float inv = 1.0f / l_i[i];
        int srow = qs + ty * 4 + i;
        float* dst = Og + ((size_t)(b * NS + srow)) * NHDIM + h * ND;
        float4 v0 = make_float4(oacc[i][0] * inv, oacc[i][1] * inv,
                                oacc[i][2] * inv, oacc[i][3] * inv);
        float4 v1 = make_float4(oacc[i][4] * inv, oacc[i][5] * inv,
                                oacc[i][6] * inv, oacc[i][7] * inv);
        *(float4*)(dst + tx * 4)      = v0;
        *(float4*)(dst + 64 + tx * 4) = v1;
    }
}

// ==================================================================== launch
extern "C" void kernel_launch(void* const* d_in, const int* in_sizes, int n_in,
                              void* d_out, int out_size)
{
    (void)in_sizes; (void)n_in; (void)out_size;
    const float* x      = (const float*)d_in[0];
    const float* w_q    = (const float*)d_in[1];
    const float* w_k    = (const float*)d_in[2];
    const float* w_v    = (const float*)d_in[3];
    const float* w_proj = (const float*)d_in[4];
    const float* b_proj = (const float*)d_in[5];
    float* out = (float*)d_out;

    cudaFuncSetAttribute(fattn, cudaFuncAttributeMaxDynamicSharedMemorySize,
                         FA_SMEM_BYTES);

    dim3 blk(256);
    // fused Q/K/V projections: grid.x = 3 * 16 column tiles
    gemm_nt<<<dim3(48, 64), blk>>>(x, w_q, w_k, w_v, nullptr, nullptr, 1);
    // causal flash attention over scratch q/k/v
    fattn<<<dim3(NS / BR, NB * NH), blk, FA_SMEM_BYTES>>>();
    // output projection + bias
    gemm_nt<<<dim3(16, 64), blk>>>(nullptr, w_proj, nullptr, nullptr, b_proj,
                                   out, 0);
}

// round 2
// speedup vs baseline: 1.8552x; 1.8552x over previous
#include <cuda_runtime.h>
#include <cstdint>

#define NB 4
#define NS 2048
#define NE 2048
#define NH 16
#define ND 128
#define NHDIM 2048
#define CH (NB*NS*NHDIM)        // 16777216
#define WN (NHDIM*NE)           // 4194304

// scratch: [q | k | v | attn_out | x_rounded | wq_r | wk_r | wv_r | wproj_r]
__device__ float g_scratch[5ll*CH + 4ll*WN];

// -------------------------------------------------------------- helpers
__device__ __forceinline__ float rna(float x) {
    uint32_t u;
    asm("cvt.rna.tf32.f32 %0, %1;" : "=r"(u) : "f"(x));
    return __uint_as_float(u);
}

__device__ __forceinline__ void mma_tf32(float* d,
    uint32_t a0, uint32_t a1, uint32_t a2, uint32_t a3,
    uint32_t b0, uint32_t b1)
{
    asm volatile(
        "mma.sync.aligned.m16n8k8.row.col.f32.tf32.tf32.f32 "
        "{%0,%1,%2,%3}, {%4,%5,%6,%7}, {%8,%9}, {%0,%1,%2,%3};\n"
        : "+f"(d[0]), "+f"(d[1]), "+f"(d[2]), "+f"(d[3])
        : "r"(a0), "r"(a1), "r"(a2), "r"(a3), "r"(b0), "r"(b1));
}

// round fp32 -> tf32-representable fp32 (RNA), vectorized
__global__ void round_tf32(const float* __restrict__ src,
                           float* __restrict__ dst, int n4)
{
    int i = blockIdx.x * blockDim.x + threadIdx.x;
    if (i < n4) {
        float4 v = ((const float4*)src)[i];
        v.x = rna(v.x); v.y = rna(v.y); v.z = rna(v.z); v.w = rna(v.w);
        ((float4*)dst)[i] = v;
    }
}

// ================================================= tensor-core GEMM (NT)
// C[m,n] = sum_k A[m,k] * W[n,k] (+ bias). Inputs pre-rounded to tf32.
// mode 1: fused QKV (W selected by bx>>4), scatter to [B,H,S,D] scratch.
// mode 0: proj, A = attn_out scratch, C = external with bias.
#define BM 128
#define BN 128
#define BK 32
#define TILEW (BM*32)           // words per tile (4096)
#define STAGEW (2*TILEW)        // words per stage (A+B)
#define GSMEM (3*STAGEW*4)      // 98304 bytes

// word offset inside a [128 x 32-word] tile; 16B-chunk xor swizzle
__device__ __forceinline__ uint32_t swzw(int m, int k4) {
    return (uint32_t)((m << 5) + ((k4 ^ ((m & 1) << 2)) << 2));
}

__global__ __launch_bounds__(256)
void gemm_tc(const float* __restrict__ Ax, const float* __restrict__ W0,
             const float* __restrict__ W1, const float* __restrict__ W2,
             const float* __restrict__ bias, float* __restrict__ Cext,
             int mode)
{
    extern __shared__ float sh[];
    const int tid  = threadIdx.x;
    const int lane = tid & 31;
    const int warp = tid >> 5;
    const int wm   = warp >> 2;          // 0..1
    const int wn   = warp & 3;           // 0..3

    int bx = blockIdx.x;
    const float* A = Ax;
    const float* W = W0;
    float* C = Cext;
    if (mode == 1) {
        int ws = bx >> 4; bx &= 15;
        W = (ws == 0) ? W0 : (ws == 1 ? W1 : W2);
        C = g_scratch + (size_t)ws * CH;
    }
    const int m0 = blockIdx.y * BM;
    const int n0 = bx * BN;
    const float* Ag = A + (size_t)m0 * NE;
    const float* Wg = W + (size_t)n0 * NE;

    const uint32_t sb = (uint32_t)__cvta_generic_to_shared(sh);

    auto stage = [&](int st, int it) {
        const int k0 = it * BK;
        uint32_t abase = sb + (uint32_t)(st * STAGEW) * 4u;
        uint32_t bbase = abase + TILEW * 4u;
        #pragma unroll
        for (int p = 0; p < 4; p++) {
            int idx = p * 256 + tid;
            int m = idx >> 3, k4 = idx & 7;
            const float* ga = Ag + (size_t)m * NE + k0 + (k4 << 2);
            uint32_t da = abase + swzw(m, k4) * 4u;
            asm volatile("cp.async.cg.shared.global [%0], [%1], 16;\n"
                         :: "r"(da), "l"(ga) : "memory");
            const float* gb = Wg + (size_t)m * NE + k0 + (k4 << 2);
            uint32_t db = bbase + swzw(m, k4) * 4u;
            asm volatile("cp.async.cg.shared.global [%0], [%1], 16;\n"
                         :: "r"(db), "l"(gb) : "memory");
        }
    };

    float Cc[4][4][4];
    #pragma unroll
    for (int mt = 0; mt < 4; mt++)
        #pragma unroll
        for (int nt = 0; nt < 4; nt++)
            #pragma unroll
            for (int q = 0; q < 4; q++) Cc[mt][nt][q] = 0.0f;

    stage(0, 0); asm volatile("cp.async.commit_group;\n" ::: "memory");
    stage(1, 1); asm volatile("cp.async.commit_group;\n" ::: "memory");

    const int NIT = NE / BK;             // 64
    for (int it = 0; it < NIT; it++) {
        asm volatile("cp.async.wait_group 1;\n" ::: "memory");
        __syncthreads();
        if (it + 2 < NIT) stage((it + 2) % 3, it + 2);
        asm volatile("cp.async.commit_group;\n" ::: "memory");

        const float* sA = sh + (size_t)(it % 3) * STAGEW;
        const float* sB = sA + TILEW;

        #pragma unroll
        for (int c = 0; c < 2; c++) {
            const int kb = c << 2;       // k4 base of 16-wide chunk
            uint32_t a[4][8], b[4][4];
            #pragma unroll
            for (int mt = 0; mt < 4; mt++) {
                int m = wm * 64 + mt * 16 + (lane >> 2);
                uint4 lo = *(const uint4*)(sA + swzw(m,     kb + (lane & 3)));
                uint4 hi = *(const uint4*)(sA + swzw(m + 8, kb + (lane & 3)));
                a[mt][0] = lo.x; a[mt][1] = hi.x; a[mt][2] = lo.y; a[mt][3] = hi.y;
                a[mt][4] = lo.z; a[mt][5] = hi.z; a[mt][6] = lo.w; a[mt][7] = hi.w;
            }
            #pragma unroll
            for (int nt = 0; nt < 4; nt++) {
                int n = wn * 32 + nt * 8 + (lane >> 2);
                uint4 bv = *(const uint4*)(sB + swzw(n, kb + (lane & 3)));
                b[nt][0] = bv.x; b[nt][1] = bv.y; b[nt][2] = bv.z; b[nt][3] = bv.w;
            }
            #pragma unroll
            for (int s = 0; s < 2; s++)
                #pragma unroll
                for (int mt = 0; mt < 4; mt++)
                    #pragma unroll
                    for (int nt = 0; nt < 4; nt++)
                        mma_tf32(Cc[mt][nt],
                                 a[mt][s*4+0], a[mt][s*4+1],
                                 a[mt][s*4+2], a[mt][s*4+3],
                                 b[nt][s*2+0], b[nt][s*2+1]);
        }
    }

    // ------------------------------------------------------------ epilogue
    if (mode == 1) {
        const int h = n0 >> 7;           // BN == ND: one head per block
        #pragma unroll
        for (int mt = 0; mt < 4; mt++) {
            int r0 = m0 + wm * 64 + mt * 16 + (lane >> 2);
            #pragma unroll
            for (int half = 0; half < 2; half++) {
                int r  = r0 + half * 8;
                int bb = r >> 11;
                int s  = r & (NS - 1);
                float* dst = C + (((size_t)(bb * NH + h)) * NS + s) * ND;
                #pragma unroll
                for (int nt = 0; nt < 4; nt++) {
                    int d = wn * 32 + nt * 8 + ((lane & 3) << 1);
                    float2 v = half ? make_float2(Cc[mt][nt][2], Cc[mt][nt][3])
                                    : make_float2(Cc[mt][nt][0], Cc[mt][nt][1]);
                    *(float2*)(dst + d) = v;
                }
            }
        }
    } else {
        #pragma unroll
        for (int mt = 0; mt < 4; mt++) {
            int r0 = m0 + wm * 64 + mt * 16 + (lane >> 2);
            #pragma unroll
            for (int half = 0; half < 2; half++) {
                int r = r0 + half * 8;
                float* dst = C + (size_t)r * NE;
                #pragma unroll
                for (int nt = 0; nt < 4; nt++) {
                    int col = n0 + wn * 32 + nt * 8 + ((lane & 3) << 1);
                    float2 v = half ? make_float2(Cc[mt][nt][2], Cc[mt][nt][3])
                                    : make_float2(Cc[mt][nt][0], Cc[mt][nt][1]);
                    v.x += bias[col];
                    v.y += bias[col + 1];
                    *(float2*)(dst + col) = v;
                }
            }
        }
    }
}

// ============================================================ Flash attention
#define BR 64
#define BC 64
#define QLD 68
#define VLD 132
#define FA_SMEM_FLOATS (2 * ND * QLD + BC * VLD + BC * QLD)
#define FA_SMEM_BYTES  (FA_SMEM_FLOATS * 4)

__global__ __launch_bounds__(256)
void fattn()
{
    extern __shared__ float sm[];
    float* Qs = sm;
    float* Ks = Qs + ND * QLD;
    float* Vs = Ks + ND * QLD;
    float* Ps = Vs + BC * VLD;

    const float* Qg = g_scratch;
    const float* Kg = g_scratch + (size_t)CH;
    const float* Vg = g_scratch + 2ll * CH;
    float*       Og = g_scratch + 3ll * CH;

    const int tid = threadIdx.x;
    const int tx  = tid & 15;
    const int ty  = tid >> 4;
    const int qs  = blockIdx.x * BR;
    const int bh  = blockIdx.y;

    const float* Qbase = Qg + (size_t)bh * NS * ND + (size_t)qs * ND;
    const float* Kbase = Kg + (size_t)bh * NS * ND;
    const float* Vbase = Vg + (size_t)bh * NS * ND;

    {
        int row = tid >> 2;
        int cl  = tid & 3;
        #pragma unroll
        for (int t = 0; t < 8; t++) {
            int c4 = t * 4 + cl;
            float4 v = *(const float4*)(Qbase + (size_t)row * ND + c4 * 4);
            Qs[(c4 * 4 + 0) * QLD + row] = v.x;
            Qs[(c4 * 4 + 1) * QLD + row] = v.y;
            Qs[(c4 * 4 + 2) * QLD + row] = v.z;
            Qs[(c4 * 4 + 3) * QLD + row] = v.w;
        }
    }

    float m_i[4], l_i[4], oacc[4][8];
    #pragma unroll
    for (int i = 0; i < 4; i++) {
        m_i[i] = -1e30f;
        l_i[i] = 0.0f;
        #pragma unroll
        for (int c = 0; c < 8; c++) oacc[i][c] = 0.0f;
    }

    const float sc = 0.08838834764831845f;
    const int nkt = (qs >> 6) + 1;

    for (int kt = 0; kt < nkt; kt++) {
        const int ks = kt * BC;
        __syncthreads();

        {
            int row = tid >> 2;
            int cl  = tid & 3;
            const float* kb = Kbase + (size_t)(ks + row) * ND;
            #pragma unroll
            for (int t = 0; t < 8; t++) {
                int c4 = t * 4 + cl;
                float4 v = *(const float4*)(kb + c4 * 4);
                Ks[(c4 * 4 + 0) * QLD + row] = v.x;
                Ks[(c4 * 4 + 1) * QLD + row] = v.y;
                Ks[(c4 * 4 + 2) * QLD + row] = v.z;
                Ks[(c4 * 4 + 3) * QLD + row] = v.w;
            }
        }
        {
            int vrow = tid >> 5;
            int vc   = tid & 31;
            #pragma unroll
            for (int t = 0; t < 8; t++) {
                int r = vrow + t * 8;
                float4 v = *(const float4*)(Vbase + (size_t)(ks + r) * ND + vc * 4);
                *(float4*)&Vs[r * VLD + vc * 4] = v;
            }
        }
        __syncthreads();

        float s[4][4];
        #pragma unroll
        for (int i = 0; i < 4; i++)
            #pragma unroll
            for (int j = 0; j < 4; j++) s[i][j] = 0.0f;

        #pragma unroll 4
        for (int d = 0; d < ND; d++) {
            float qv[4], kv[4];
            *(float4*)qv = *(const float4*)&Qs[d * QLD + ty * 4];
            *(float4*)kv = *(const float4*)&Ks[d * QLD + tx * 4];
            #pragma unroll
            for (int i = 0; i < 4; i++)
                #pragma unroll
                for (int j = 0; j < 4; j++)
                    s[i][j] = fmaf(qv[i], kv[j], s[i][j]);
        }

        const bool diag = (ks == qs);
        float z[4][4];
        #pragma unroll
        for (int i = 0; i < 4; i++)
            #pragma unroll
            for (int j = 0; j < 4; j++) {
                float val = s[i][j] * sc;
                if (diag && (tx * 4 + j) > (ty * 4 + i)) val = -1e30f;
                z[i][j] = val;
            }

        float mt[4];
        #pragma unroll
        for (int i = 0; i < 4; i++)
            mt[i] = fmaxf(fmaxf(z[i][0], z[i][1]), fmaxf(z[i][2], z[i][3]));
        #pragma unroll
        for (int off = 8; off > 0; off >>= 1)
            #pragma unroll
            for (int i = 0; i < 4; i++)
                mt[i] = fmaxf(mt[i], __shfl_xor_sync(0xFFFFFFFFu, mt[i], off));

        float alpha[4], rs[4], p[4][4];
        #pragma unroll
        for (int i = 0; i < 4; i++) {
            float mn = fmaxf(m_i[i], mt[i]);
            alpha[i] = __expf(m_i[i] - mn);
            m_i[i] = mn;
            rs[i] = 0.0f;
            #pragma unroll
            for (int j = 0; j < 4; j++) {
                p[i][j] = __expf(z[i][j] - mn);
                rs[i] += p[i][j];
            }
        }
        #pragma unroll
        for (int off = 8; off > 0; off >>= 1)
            #pragma unroll
            for (int i = 0; i < 4; i++)
                rs[i] += __shfl_xor_sync(0xFFFFFFFFu, rs[i], off);

        #pragma unroll
        for (int i = 0; i < 4; i++) {
            l_i[i] = l_i[i] * alpha[i] + rs[i];
            #pragma unroll
            for (int c = 0; c < 8; c++) oacc[i][c] *= alpha[i];
        }

        #pragma unroll
        for (int i = 0; i < 4; i++)
            #pragma unroll
            for (int j = 0; j < 4; j++)
                Ps[(tx * 4 + j) * QLD + (ty * 4 + i)] = p[i][j];
        __syncthreads();

        #pragma unroll 4
        for (int j = 0; j < BC; j++) {
            float pv[4], vv[8];
            *(float4*)pv     = *(const float4*)&Ps[j * QLD + ty * 4];
            *(float4*)&vv[0] = *(const float4*)&Vs[j * VLD + tx * 4];
            *(float4*)&vv[4] = *(const float4*)&Vs[j * VLD + 64 + tx * 4];
            #pragma unroll
            for (int i = 0; i < 4; i++)
                #pragma unroll
                for (int c = 0; c < 8; c++)
                    oacc[i][c] = fmaf(pv[i], vv[c], oacc[i][c]);
        }
    }

    // write O (pre-rounded to tf32 for the proj tensor-core GEMM)
    const int b = bh >> 4;
    const int h = bh & 15;
    #pragma unroll
    for (int i = 0; i < 4; i++) {
        float inv = 1.0f / l_i[i];
        int srow = qs + ty * 4 + i;
        float* dst = Og + ((size_t)(b * NS + srow)) * NHDIM + h * ND;
        float4 v0 = make_float4(rna(oacc[i][0] * inv), rna(oacc[i][1] * inv),
                                rna(oacc[i][2] * inv), rna(oacc[i][3] * inv));
        float4 v1 = make_float4(rna(oacc[i][4] * inv), rna(oacc[i][5] * inv),
                                rna(oacc[i][6] * inv), rna(oacc[i][7] * inv));
        *(float4*)(dst + tx * 4)      = v0;
        *(float4*)(dst + 64 + tx * 4) = v1;
    }
}

// ==================================================================== launch
extern "C" void kernel_launch(void* const* d_in, const int* in_sizes, int n_in,
                              void* d_out, int out_size)
{
    (void)in_sizes; (void)n_in; (void)out_size;
    const float* x      = (const float*)d_in[0];
    const float* w_q    = (const float*)d_in[1];
    const float* w_k    = (const float*)d_in[2];
    const float* w_v    = (const float*)d_in[3];
    const float* w_proj = (const float*)d_in[4];
    const float* b_proj = (const float*)d_in[5];
    float* out = (float*)d_out;

    cudaFuncSetAttribute(fattn, cudaFuncAttributeMaxDynamicSharedMemorySize,
                         FA_SMEM_BYTES);
    cudaFuncSetAttribute(gemm_tc, cudaFuncAttributeMaxDynamicSharedMemorySize,
                         GSMEM);

    float* base = nullptr;
    cudaGetSymbolAddress((void**)&base, g_scratch);
    float* xr = base + 4ll * CH;
    float* wr = base + 5ll * CH;

    // pre-round all GEMM inputs to tf32 (RNA)
    round_tf32<<<(CH/4 + 255)/256, 256>>>(x, xr, CH/4);
    round_tf32<<<(WN/4 + 255)/256, 256>>>(w_q,    wr,          WN/4);
    round_tf32<<<(WN/4 + 255)/256, 256>>>(w_k,    wr + WN,     WN/4);
    round_tf32<<<(WN/4 + 255)/256, 256>>>(w_v,    wr + 2ll*WN, WN/4);
    round_tf32<<<(WN/4 + 255)/256, 256>>>(w_proj, wr + 3ll*WN, WN/4);

    dim3 blk(256);
    // fused QKV projections on tensor cores
    gemm_tc<<<dim3(48, 64), blk, GSMEM>>>(xr, wr, wr + WN, wr + 2ll*WN,
                                          nullptr, nullptr, 1);
    // causal flash attention (fp32)
    fattn<<<dim3(NS / BR, NB * NH), blk, FA_SMEM_BYTES>>>();
    // output projection + bias on tensor cores
    gemm_tc<<<dim3(16, 64), blk, GSMEM>>>(base + 3ll*CH, wr + 3ll*WN, nullptr,
                                          nullptr, b_proj, out, 0);
}

// round 3
// speedup vs baseline: 1.8563x; 1.0006x over previous
#include <cuda_runtime.h>
#include <cstdint>

#define NB 4
#define NS 2048
#define NE 2048
#define NH 16
#define ND 128
#define NHDIM 2048
#define CH (NB*NS*NHDIM)        // 16777216
#define WN (NHDIM*NE)           // 4194304

// scratch: [q | k | v | attn_out | x_rounded | wq_r | wk_r | wv_r | wproj_r]
__device__ float g_scratch[5ll*CH + 4ll*WN];

// -------------------------------------------------------------- helpers
__device__ __forceinline__ float rna(float x) {
    uint32_t u;
    asm("cvt.rna.tf32.f32 %0, %1;" : "=r"(u) : "f"(x));
    return __uint_as_float(u);
}

__device__ __forceinline__ void mma_tf32(float* d,
    uint32_t a0, uint32_t a1, uint32_t a2, uint32_t a3,
    uint32_t b0, uint32_t b1)
{
    asm volatile(
        "mma.sync.aligned.m16n8k8.row.col.f32.tf32.tf32.f32 "
        "{%0,%1,%2,%3}, {%4,%5,%6,%7}, {%8,%9}, {%0,%1,%2,%3};\n"
        : "+f"(d[0]), "+f"(d[1]), "+f"(d[2]), "+f"(d[3])
        : "r"(a0), "r"(a1), "r"(a2), "r"(a3), "r"(b0), "r"(b1));
}

// round fp32 -> tf32-representable fp32 (RNA), vectorized
__global__ void round_tf32(const float* __restrict__ src,
                           float* __restrict__ dst, int n4)
{
    int i = blockIdx.x * blockDim.x + threadIdx.x;
    if (i < n4) {
        float4 v = ((const float4*)src)[i];
        v.x = rna(v.x); v.y = rna(v.y); v.z = rna(v.z); v.w = rna(v.w);
        ((float4*)dst)[i] = v;
    }
}

// ================================================= tensor-core GEMM (NT)
// C[m,n] = sum_k A[m,k] * W[n,k] (+ bias). Inputs pre-rounded to tf32.
// mode 1: fused QKV (W selected by bx>>4), scatter to [B,H,S,D] scratch.
// mode 0: proj, A = attn_out scratch, C = external with bias.
#define BM 128
#define BN 128
#define BK 32
#define TILEW (BM*32)           // words per tile (4096)
#define STAGEW (2*TILEW)        // words per stage (A+B)
#define GSMEM (3*STAGEW*4)      // 98304 bytes

// word offset inside a [128 x 32-word] tile; 16B-chunk xor swizzle
__device__ __forceinline__ uint32_t swzw(int m, int k4) {
    return (uint32_t)((m << 5) + ((k4 ^ ((m & 1) << 2)) << 2));
}

__global__ __launch_bounds__(256)
void gemm_tc(const float* __restrict__ Ax, const float* __restrict__ W0,
             const float* __restrict__ W1, const float* __restrict__ W2,
             const float* __restrict__ bias, float* __restrict__ Cext,
             int mode)
{
    extern __shared__ float sh[];
    const int tid  = threadIdx.x;
    const int lane = tid & 31;
    const int warp = tid >> 5;
    const int wm   = warp >> 2;          // 0..1
    const int wn   = warp & 3;           // 0..3

    int bx = blockIdx.x;
    const float* A = Ax;
    const float* W = W0;
    float* C = Cext;
    if (mode == 1) {
        int ws = bx >> 4; bx &= 15;
        W = (ws == 0) ? W0 : (ws == 1 ? W1 : W2);
        C = g_scratch + (size_t)ws * CH;
    }
    const int m0 = blockIdx.y * BM;
    const int n0 = bx * BN;
    const float* Ag = A + (size_t)m0 * NE;
    const float* Wg = W + (size_t)n0 * NE;

    const uint32_t sb = (uint32_t)__cvta_generic_to_shared(sh);

    auto stage = [&](int st, int it) {
        const int k0 = it * BK;
        uint32_t abase = sb + (uint32_t)(st * STAGEW) * 4u;
        uint32_t bbase = abase + TILEW * 4u;
        #pragma unroll
        for (int p = 0; p < 4; p++) {
            int idx = p * 256 + tid;
            int m = idx >> 3, k4 = idx & 7;
            const float* ga = Ag + (size_t)m * NE + k0 + (k4 << 2);
            uint32_t da = abase + swzw(m, k4) * 4u;
            asm volatile("cp.async.cg.shared.global [%0], [%1], 16;\n"
                         :: "r"(da), "l"(ga) : "memory");
            const float* gb = Wg + (size_t)m * NE + k0 + (k4 << 2);
            uint32_t db = bbase + swzw(m, k4) * 4u;
            asm volatile("cp.async.cg.shared.global [%0], [%1], 16;\n"
                         :: "r"(db), "l"(gb) : "memory");
        }
    };

    float Cc[4][4][4];
    #pragma unroll
    for (int mt = 0; mt < 4; mt++)
        #pragma unroll
        for (int nt = 0; nt < 4; nt++)
            #pragma unroll
            for (int q = 0; q < 4; q++) Cc[mt][nt][q] = 0.0f;

    stage(0, 0); asm volatile("cp.async.commit_group;\n" ::: "memory");
    stage(1, 1); asm volatile("cp.async.commit_group;\n" ::: "memory");

    const int NIT = NE / BK;             // 64
    for (int it = 0; it < NIT; it++) {
        asm volatile("cp.async.wait_group 1;\n" ::: "memory");
        __syncthreads();
        if (it + 2 < NIT) stage((it + 2) % 3, it + 2);
        asm volatile("cp.async.commit_group;\n" ::: "memory");

        const float* sA = sh + (size_t)(it % 3) * STAGEW;
        const float* sB = sA + TILEW;

        #pragma unroll
        for (int c = 0; c < 2; c++) {
            const int kb = c << 2;       // k4 base of 16-wide chunk
            uint32_t a[4][8], b[4][4];
            #pragma unroll
            for (int mt = 0; mt < 4; mt++) {
                int m = wm * 64 + mt * 16 + (lane >> 2);
                uint4 lo = *(const uint4*)(sA + swzw(m,     kb + (lane & 3)));
                uint4 hi = *(const uint4*)(sA + swzw(m + 8, kb + (lane & 3)));
                a[mt][0] = lo.x; a[mt][1] = hi.x; a[mt][2] = lo.y; a[mt][3] = hi.y;
                a[mt][4] = lo.z; a[mt][5] = hi.z; a[mt][6] = lo.w; a[mt][7] = hi.w;
            }
            #pragma unroll
            for (int nt = 0; nt < 4; nt++) {
                int n = wn * 32 + nt * 8 + (lane >> 2);
                uint4 bv = *(const uint4*)(sB + swzw(n, kb + (lane & 3)));
                b[nt][0] = bv.x; b[nt][1] = bv.y; b[nt][2] = bv.z; b[nt][3] = bv.w;
            }
            #pragma unroll
            for (int s = 0; s < 2; s++)
                #pragma unroll
                for (int mt = 0; mt < 4; mt++)
                    #pragma unroll
                    for (int nt = 0; nt < 4; nt++)
                        mma_tf32(Cc[mt][nt],
                                 a[mt][s*4+0], a[mt][s*4+1],
                                 a[mt][s*4+2], a[mt][s*4+3],
                                 b[nt][s*2+0], b[nt][s*2+1]);
        }
    }

    // ------------------------------------------------------------ epilogue
    if (mode == 1) {
        const int h = n0 >> 7;           // BN == ND: one head per block
        #pragma unroll
        for (int mt = 0; mt < 4; mt++) {
            int r0 = m0 + wm * 64 + mt * 16 + (lane >> 2);
            #pragma unroll
            for (int half = 0; half < 2; half++) {
                int r  = r0 + half * 8;
                int bb = r >> 11;
                int s  = r & (NS - 1);
                float* dst = C + (((size_t)(bb * NH + h)) * NS + s) * ND;
                #pragma unroll
                for (int nt = 0; nt < 4; nt++) {
                    int d = wn * 32 + nt * 8 + ((lane & 3) << 1);
                    float2 v = half ? make_float2(Cc[mt][nt][2], Cc[mt][nt][3])
                                    : make_float2(Cc[mt][nt][0], Cc[mt][nt][1]);
                    *(float2*)(dst + d) = v;
                }
            }
        }
    } else {
        #pragma unroll
        for (int mt = 0; mt < 4; mt++) {
            int r0 = m0 + wm * 64 + mt * 16 + (lane >> 2);
            #pragma unroll
            for (int half = 0; half < 2; half++) {
                int r = r0 + half * 8;
                float* dst = C + (size_t)r * NE;
                #pragma unroll
                for (int nt = 0; nt < 4; nt++) {
                    int col = n0 + wn * 32 + nt * 8 + ((lane & 3) << 1);
                    float2 v = half ? make_float2(Cc[mt][nt][2], Cc[mt][nt][3])
                                    : make_float2(Cc[mt][nt][0], Cc[mt][nt][1]);
                    v.x += bias[col];
                    v.y += bias[col + 1];
                    *(float2*)(dst + col) = v;
                }
            }
        }
    }
}

// ============================================================ Flash attention
#define BR 64
#define BC 64
#define QLD 68
#define VLD 132
#define FA_SMEM_FLOATS (2 * ND * QLD + BC * VLD + BC * QLD)
#define FA_SMEM_BYTES  (FA_SMEM_FLOATS * 4)

__global__ __launch_bounds__(256)
void fattn()
{
    extern __shared__ float sm[];
    float* Qs = sm;
    float* Ks = Qs + ND * QLD;
    float* Vs = Ks + ND * QLD;
    float* Ps = Vs + BC * VLD;

    const float* Qg = g_scratch;
    const float* Kg = g_scratch + (size_t)CH;
    const float* Vg = g_scratch + 2ll * CH;
    float*       Og = g_scratch + 3ll * CH;

    const int tid = threadIdx.x;
    const int tx  = tid & 15;
    const int ty  = tid >> 4;
    const int qs  = blockIdx.x * BR;
    const int bh  = blockIdx.y;

    const float* Qbase = Qg + (size_t)bh * NS * ND + (size_t)qs * ND;
    const float* Kbase = Kg + (size_t)bh * NS * ND;
    const float* Vbase = Vg + (size_t)bh * NS * ND;

    {
        int row = tid >> 2;
        int cl  = tid & 3;
        #pragma unroll
        for (int t = 0; t < 8; t++) {
            int c4 = t * 4 + cl;
            float4 v = *(const float4*)(Qbase + (size_t)row * ND + c4 * 4);
            Qs[(c4 * 4 + 0) * QLD + row] = v.x;
            Qs[(c4 * 4 + 1) * QLD + row] = v.y;
            Qs[(c4 * 4 + 2) * QLD + row] = v.z;
            Qs[(c4 * 4 + 3) * QLD + row] = v.w;
        }
    }

    float m_i[4], l_i[4], oacc[4][8];
    #pragma unroll
    for (int i = 0; i < 4; i++) {
        m_i[i] = -1e30f;
        l_i[i] = 0.0f;
        #pragma unroll
        for (int c = 0; c < 8; c++) oacc[i][c] = 0.0f;
    }

    const float sc = 0.08838834764831845f;
    const int nkt = (qs >> 6) + 1;

    for (int kt = 0; kt < nkt; kt++) {
        const int ks = kt * BC;
        __syncthreads();

        {
            int row = tid >> 2;
            int cl  = tid & 3;
            const float* kb = Kbase + (size_t)(ks + row) * ND;
            #pragma unroll
            for (int t = 0; t < 8; t++) {
                int c4 = t * 4 + cl;
                float4 v = *(const float4*)(kb + c4 * 4);
                Ks[(c4 * 4 + 0) * QLD + row] = v.x;
                Ks[(c4 * 4 + 1) * QLD + row] = v.y;
                Ks[(c4 * 4 + 2) * QLD + row] = v.z;
                Ks[(c4 * 4 + 3) * QLD + row] = v.w;
            }
        }
        {
            int vrow = tid >> 5;
            int vc   = tid & 31;
            #pragma unroll
            for (int t = 0; t < 8; t++) {
                int r = vrow + t * 8;
                float4 v = *(const float4*)(Vbase + (size_t)(ks + r) * ND + vc * 4);
                *(float4*)&Vs[r * VLD + vc * 4] = v;
            }
        }
        __syncthreads();

        float s[4][4];
        #pragma unroll
        for (int i = 0; i < 4; i++)
            #pragma unroll
            for (int j = 0; j < 4; j++) s[i][j] = 0.0f;

        #pragma unroll 4
        for (int d = 0; d < ND; d++) {
            float qv[4], kv[4];
            *(float4*)qv = *(const float4*)&Qs[d * QLD + ty * 4];
            *(float4*)kv = *(const float4*)&Ks[d * QLD + tx * 4];
            #pragma unroll
            for (int i = 0; i < 4; i++)
                #pragma unroll
                for (int j = 0; j < 4; j++)
                    s[i][j] = fmaf(qv[i], kv[j], s[i][j]);
        }

        const bool diag = (ks == qs);
        float z[4][4];
        #pragma unroll
        for (int i = 0; i < 4; i++)
            #pragma unroll
            for (int j = 0; j < 4; j++) {
                float val = s[i][j] * sc;
                if (diag && (tx * 4 + j) > (ty * 4 + i)) val = -1e30f;
                z[i][j] = val;
            }

        float mt[4];
        #pragma unroll
        for (int i = 0; i < 4; i++)
            mt[i] = fmaxf(fmaxf(z[i][0], z[i][1]), fmaxf(z[i][2], z[i][3]));
        #pragma unroll
        for (int off = 8; off > 0; off >>= 1)
            #pragma unroll
            for (int i = 0; i < 4; i++)
                mt[i] = fmaxf(mt[i], __shfl_xor_sync(0xFFFFFFFFu, mt[i], off));

        float alpha[4], rs[4], p[4][4];
        #pragma unroll
        for (int i = 0; i < 4; i++) {
            float mn = fmaxf(m_i[i], mt[i]);
            alpha[i] = __expf(m_i[i] - mn);
            m_i[i] = mn;
            rs[i] = 0.0f;
            #pragma unroll
            for (int j = 0; j < 4; j++) {
                p[i][j] = __expf(z[i][j] - mn);
                rs[i] += p[i][j];
            }
        }
        #pragma unroll
        for (int off = 8; off > 0; off >>= 1)
            #pragma unroll
            for (int i = 0; i < 4; i++)
                rs[i] += __shfl_xor_sync(0xFFFFFFFFu, rs[i], off);

        #pragma unroll
        for (int i = 0; i < 4; i++) {
            l_i[i] = l_i[i] * alpha[i] + rs[i];
            #pragma unroll
            for (int c = 0; c < 8; c++) oacc[i][c] *= alpha[i];
        }

        #pragma unroll
        for (int i = 0; i < 4; i++)
            #pragma unroll
            for (int j = 0; j < 4; j++)
                Ps[(tx * 4 + j) * QLD + (ty * 4 + i)] = p[i][j];
        __syncthreads();

        #pragma unroll 4
        for (int j = 0; j < BC; j++) {
            float pv[4], vv[8];
            *(float4*)pv     = *(const float4*)&Ps[j * QLD + ty * 4];
            *(float4*)&vv[0] = *(const float4*)&Vs[j * VLD + tx * 4];
            *(float4*)&vv[4] = *(const float4*)&Vs[j * VLD + 64 + tx * 4];
            #pragma unroll
            for (int i = 0; i < 4; i++)
                #pragma unroll
                for (int c = 0; c < 8; c++)
                    oacc[i][c] = fmaf(pv[i], vv[c], oacc[i][c]);
        }
    }

    // write O (pre-rounded to tf32 for the proj tensor-core GEMM)
    const int b = bh >> 4;
    const int h = bh & 15;
    #pragma unroll
    for (int i = 0; i < 4; i++) {
        float inv = 1.0f / l_i[i];
        int srow = qs + ty * 4 + i;
        float* dst = Og + ((size_t)(b * NS + srow)) * NHDIM + h * ND;
        float4 v0 = make_float4(rna(oacc[i][0] * inv), rna(oacc[i][1] * inv),
                                rna(oacc[i][2] * inv), rna(oacc[i][3] * inv));
        float4 v1 = make_float4(rna(oacc[i][4] * inv), rna(oacc[i][5] * inv),
                                rna(oacc[i][6] * inv), rna(oacc[i][7] * inv));
        *(float4*)(dst + tx * 4)      = v0;
        *(float4*)(dst + 64 + tx * 4) = v1;
    }
}

// ==================================================================== launch
extern "C" void kernel_launch(void* const* d_in, const int* in_sizes, int n_in,
                              void* d_out, int out_size)
{
    (void)in_sizes; (void)n_in; (void)out_size;
    const float* x      = (const float*)d_in[0];
    const float* w_q    = (const float*)d_in[1];
    const float* w_k    = (const float*)d_in[2];
    const float* w_v    = (const float*)d_in[3];
    const float* w_proj = (const float*)d_in[4];
    const float* b_proj = (const float*)d_in[5];
    float* out = (float*)d_out;

    cudaFuncSetAttribute(fattn, cudaFuncAttributeMaxDynamicSharedMemorySize,
                         FA_SMEM_BYTES);
    cudaFuncSetAttribute(gemm_tc, cudaFuncAttributeMaxDynamicSharedMemorySize,
                         GSMEM);

    float* base = nullptr;
    cudaGetSymbolAddress((void**)&base, g_scratch);
    float* xr = base + 4ll * CH;
    float* wr = base + 5ll * CH;

    // pre-round all GEMM inputs to tf32 (RNA)
    round_tf32<<<(CH/4 + 255)/256, 256>>>(x, xr, CH/4);
    round_tf32<<<(WN/4 + 255)/256, 256>>>(w_q,    wr,          WN/4);
    round_tf32<<<(WN/4 + 255)/256, 256>>>(w_k,    wr + WN,     WN/4);
    round_tf32<<<(WN/4 + 255)/256, 256>>>(w_v,    wr + 2ll*WN, WN/4);
    round_tf32<<<(WN/4 + 255)/256, 256>>>(w_proj, wr + 3ll*WN, WN/4);

    dim3 blk(256);
    // fused QKV projections on tensor cores
    gemm_tc<<<dim3(48, 64), blk, GSMEM>>>(xr, wr, wr + WN, wr + 2ll*WN,
                                          nullptr, nullptr, 1);
    // causal flash attention (fp32)
    fattn<<<dim3(NS / BR, NB * NH), blk, FA_SMEM_BYTES>>>();
    // output projection + bias on tensor cores
    gemm_tc<<<dim3(16, 64), blk, GSMEM>>>(base + 3ll*CH, wr + 3ll*WN, nullptr,
                                          nullptr, b_proj, out, 0);
}

// round 4
// speedup vs baseline: 3.2120x; 1.7304x over previous
#include <cuda_runtime.h>
#include <cstdint>

#define NB 4
#define NS 2048
#define NE 2048
#define NH 16
#define ND 128
#define NHDIM 2048
#define CH (NB*NS*NHDIM)
#define WN (NHDIM*NE)
#define QK_SCALE 0.08838834764831845f

// planes: 0 q~ (scaled,rna)  1 k~  2 vT [bh][d][s]  3 attn_out  4 x_r, then 4 weights
__device__ float g_scratch[5ll*CH + 4ll*WN];

__device__ __forceinline__ float rna(float x) {
    uint32_t u; asm("cvt.rna.tf32.f32 %0, %1;" : "=r"(u) : "f"(x));
    return __uint_as_float(u);
}
__device__ __forceinline__ void mma_tf32(float* d,
    uint32_t a0, uint32_t a1, uint32_t a2, uint32_t a3, uint32_t b0, uint32_t b1)
{
    asm volatile(
        "mma.sync.aligned.m16n8k8.row.col.f32.tf32.tf32.f32 "
        "{%0,%1,%2,%3}, {%4,%5,%6,%7}, {%8,%9}, {%0,%1,%2,%3};\n"
        : "+f"(d[0]), "+f"(d[1]), "+f"(d[2]), "+f"(d[3])
        : "r"(a0), "r"(a1), "r"(a2), "r"(a3), "r"(b0), "r"(b1));
}
__device__ __forceinline__ void cpa16(uint32_t dst, const void* src) {
    asm volatile("cp.async.cg.shared.global [%0], [%1], 16;\n" :: "r"(dst), "l"(src) : "memory");
}
#define CP_COMMIT asm volatile("cp.async.commit_group;\n" ::: "memory")
#define CP_WAIT1  asm volatile("cp.async.wait_group 1;\n" ::: "memory")

__global__ void round_tf32(const float* __restrict__ src, float* __restrict__ dst, int n4) {
    int i = blockIdx.x * blockDim.x + threadIdx.x;
    if (i < n4) {
        float4 v = ((const float4*)src)[i];
        v.x = rna(v.x); v.y = rna(v.y); v.z = rna(v.z); v.w = rna(v.w);
        ((float4*)dst)[i] = v;
    }
}

// ================================================= tensor-core GEMM (NT)
#define TILEW (128*32)
#define STAGEW (2*TILEW)
#define GSMEM (3*STAGEW*4)

__device__ __forceinline__ uint32_t swzw(int m, int k4) {
    return (uint32_t)((m << 5) + ((k4 ^ ((m & 1) << 2)) << 2));
}

__global__ __launch_bounds__(256)
void gemm_tc(const float* __restrict__ Ax, const float* __restrict__ W0,
             const float* __restrict__ W1, const float* __restrict__ W2,
             const float* __restrict__ bias, float* __restrict__ Cext, int mode)
{
    extern __shared__ float sh[];
    const int tid = threadIdx.x, lane = tid & 31, warp = tid >> 5;
    const int wm = warp >> 2, wn = warp & 3;

    int bx = blockIdx.x;
    const float* A = Ax;
    const float* W = W0;
    int wsel = -1;
    if (mode == 1) {
        wsel = bx >> 4; bx &= 15;
        W = (wsel == 0) ? W0 : (wsel == 1 ? W1 : W2);
    }
    const int m0 = blockIdx.y * 128, n0 = bx * 128;
    const float* Ag = A + (size_t)m0 * NE;
    const float* Wg = W + (size_t)n0 * NE;
    const uint32_t sb = (uint32_t)__cvta_generic_to_shared(sh);

    auto stage = [&](int st, int it) {
        const int k0 = it * 32;
        uint32_t ab = sb + (uint32_t)(st * STAGEW) * 4u, bb = ab + TILEW * 4u;
        #pragma unroll
        for (int p = 0; p < 4; p++) {
            int idx = p * 256 + tid, m = idx >> 3, k4 = idx & 7;
            cpa16(ab + swzw(m, k4) * 4u, Ag + (size_t)m * NE + k0 + (k4 << 2));
            cpa16(bb + swzw(m, k4) * 4u, Wg + (size_t)m * NE + k0 + (k4 << 2));
        }
    };

    float Cc[4][4][4];
    #pragma unroll
    for (int mt = 0; mt < 4; mt++)
        #pragma unroll
        for (int nt = 0; nt < 4; nt++)
            #pragma unroll
            for (int q = 0; q < 4; q++) Cc[mt][nt][q] = 0.0f;

    stage(0, 0); CP_COMMIT;
    stage(1, 1); CP_COMMIT;

    const int NIT = NE / 32;
    for (int it = 0; it < NIT; it++) {
        CP_WAIT1;
        __syncthreads();
        if (it + 2 < NIT) stage((it + 2) % 3, it + 2);
        CP_COMMIT;
        const float* sA = sh + (size_t)(it % 3) * STAGEW;
        const float* sB = sA + TILEW;
        #pragma unroll
        for (int c = 0; c < 2; c++) {
            const int kb = c << 2;
            uint32_t a[4][8], b[4][4];
            #pragma unroll
            for (int mt = 0; mt < 4; mt++) {
                int m = wm * 64 + mt * 16 + (lane >> 2);
                uint4 lo = *(const uint4*)(sA + swzw(m,     kb + (lane & 3)));
                uint4 hi = *(const uint4*)(sA + swzw(m + 8, kb + (lane & 3)));
                a[mt][0]=lo.x; a[mt][1]=hi.x; a[mt][2]=lo.y; a[mt][3]=hi.y;
                a[mt][4]=lo.z; a[mt][5]=hi.z; a[mt][6]=lo.w; a[mt][7]=hi.w;
            }
            #pragma unroll
            for (int nt = 0; nt < 4; nt++) {
                int n = wn * 32 + nt * 8 + (lane >> 2);
                uint4 bv = *(const uint4*)(sB + swzw(n, kb + (lane & 3)));
                b[nt][0]=bv.x; b[nt][1]=bv.y; b[nt][2]=bv.z; b[nt][3]=bv.w;
            }
            #pragma unroll
            for (int s = 0; s < 2; s++)
                #pragma unroll
                for (int mt = 0; mt < 4; mt++)
                    #pragma unroll
                    for (int nt = 0; nt < 4; nt++)
                        mma_tf32(Cc[mt][nt], a[mt][s*4+0], a[mt][s*4+1],
                                 a[mt][s*4+2], a[mt][s*4+3], b[nt][s*2+0], b[nt][s*2+1]);
        }
    }

    if (mode == 1) {
        const int h = n0 >> 7;
        if (wsel <= 1) {   // q (scaled) / k, rna'd, [bh][s][d]
            float* plane = g_scratch + (size_t)wsel * CH;
            const float mul = (wsel == 0) ? QK_SCALE : 1.0f;
            #pragma unroll
            for (int mt = 0; mt < 4; mt++)
                #pragma unroll
                for (int half = 0; half < 2; half++) {
                    int r = m0 + wm * 64 + mt * 16 + (lane >> 2) + half * 8;
                    int bb2 = r >> 11, s = r & (NS - 1);
                    float* dst = plane + (((size_t)(bb2 * NH + h)) * NS + s) * ND;
                    #pragma unroll
                    for (int nt = 0; nt < 4; nt++) {
                        int d = wn * 32 + nt * 8 + ((lane & 3) << 1);
                        float2 v = half ? make_float2(Cc[mt][nt][2], Cc[mt][nt][3])
                                        : make_float2(Cc[mt][nt][0], Cc[mt][nt][1]);
                        v.x = rna(v.x * mul); v.y = rna(v.y * mul);
                        *(float2*)(dst + d) = v;
                    }
                }
        } else {           // V: smem transpose -> [bh][d][s], rna'd
            float* tr = sh;
            __syncthreads();
            #pragma unroll
            for (int mt = 0; mt < 4; mt++)
                #pragma unroll
                for (int half = 0; half < 2; half++) {
                    int rl = wm * 64 + mt * 16 + (lane >> 2) + half * 8;
                    #pragma unroll
                    for (int nt = 0; nt < 4; nt++) {
                        int col = wn * 32 + nt * 8 + ((lane & 3) << 1);
                        float2 v = half ? make_float2(Cc[mt][nt][2], Cc[mt][nt][3])
                                        : make_float2(Cc[mt][nt][0], Cc[mt][nt][1]);
                        *(float2*)&tr[rl * 132 + col] = v;
                    }
                }
            __syncthreads();
            const int d = tid >> 1, s0 = (tid & 1) << 6;
            const int bb2 = m0 >> 11, sbase = m0 & (NS - 1);
            float* dst = g_scratch + 2ll * CH
                       + ((size_t)((bb2 * NH + h) * ND + d)) * NS + sbase + s0;
            #pragma unroll
            for (int i = 0; i < 64; i += 4) {
                float4 vv;
                vv.x = rna(tr[(s0 + i + 0) * 132 + d]);
                vv.y = rna(tr[(s0 + i + 1) * 132 + d]);
                vv.z = rna(tr[(s0 + i + 2) * 132 + d]);
                vv.w = rna(tr[(s0 + i + 3) * 132 + d]);
                *(float4*)(dst + i) = vv;
            }
        }
    } else {
        #pragma unroll
        for (int mt = 0; mt < 4; mt++)
            #pragma unroll
            for (int half = 0; half < 2; half++) {
                int r = m0 + wm * 64 + mt * 16 + (lane >> 2) + half * 8;
                float* dst = Cext + (size_t)r * NE;
                #pragma unroll
                for (int nt = 0; nt < 4; nt++) {
                    int col = n0 + wn * 32 + nt * 8 + ((lane & 3) << 1);
                    float2 v = half ? make_float2(Cc[mt][nt][2], Cc[mt][nt][3])
                                    : make_float2(Cc[mt][nt][0], Cc[mt][nt][1]);
                    v.x += bias[col]; v.y += bias[col + 1];
                    *(float2*)(dst + col) = v;
                }
            }
    }
}

// ====================================== tensor-core flash attention
// Br=128 (8 warps x 16 rows), Bc=64, K/VT double-buffered.
#define QW 16384
#define KW 8192
#define VW 8192
#define FA2_SMEM ((QW + 2*KW + 2*VW + 8192) * 4)   // 229376 B

__device__ __forceinline__ uint32_t swzq(int m, int k4) {   // 128-word rows
    return (uint32_t)((m << 7) + ((k4 ^ ((m & 1) << 2)) << 2));
}
__device__ __forceinline__ uint32_t swzv(int d, int k4) {   // 64-word rows
    return (uint32_t)((d << 6) + ((k4 ^ ((d & 1) << 2)) << 2));
}

__global__ __launch_bounds__(256)
void fattn_tc()
{
    extern __shared__ float fs[];
    float* smQ = fs;
    float* smK = fs + QW;
    float* smV = fs + QW + 2 * KW;
    float* smP = fs + QW + 2 * KW + 2 * VW;

    const int tid = threadIdx.x, lane = tid & 31, w = tid >> 5;
    const int g = lane >> 2, q = lane & 3, r0 = w * 16;
    const int qt = (int)gridDim.x - 1 - (int)blockIdx.x;   // heavy first
    const int qs = qt * 128;
    const int bh = blockIdx.y;

    const float* Qg = g_scratch + (size_t)bh * NS * ND + (size_t)qs * ND;
    const float* Kg = g_scratch + (size_t)CH + (size_t)bh * NS * ND;
    const float* Vg = g_scratch + 2ll * CH + (size_t)bh * ND * NS;
    float*       Og = g_scratch + 3ll * CH;
    const uint32_t sb = (uint32_t)__cvta_generic_to_shared(fs);

    auto stage_kv = [&](int it, int buf) {
        const int ks = it * 64;
        #pragma unroll
        for (int p = 0; p < 8; p++) {           // K: 64 rows x 32 chunks
            int idx = p * 256 + tid, m = idx >> 5, k4 = idx & 31;
            cpa16(sb + (QW + buf * KW + swzq(m, k4)) * 4u,
                  Kg + (size_t)(ks + m) * ND + (k4 << 2));
        }
        #pragma unroll
        for (int p = 0; p < 8; p++) {           // VT: 128 d x 16 chunks
            int idx = p * 256 + tid, d = idx >> 4, k4 = idx & 15;
            cpa16(sb + (QW + 2 * KW + buf * VW + swzv(d, k4)) * 4u,
                  Vg + (size_t)d * NS + ks + (k4 << 2));
        }
    };

    #pragma unroll
    for (int p = 0; p < 16; p++) {              // Q once
        int idx = p * 256 + tid, m = idx >> 5, k4 = idx & 31;
        cpa16(sb + swzq(m, k4) * 4u, Qg + (size_t)m * ND + (k4 << 2));
    }
    CP_COMMIT;
    stage_kv(0, 0); CP_COMMIT;

    float m_a = -1e30f, m_b = -1e30f, l_a = 0.0f, l_b = 0.0f;
    float O[16][4];
    #pragma unroll
    for (int dt = 0; dt < 16; dt++)
        #pragma unroll
        for (int c = 0; c < 4; c++) O[dt][c] = 0.0f;

    float* wp = smP + w * 16 * 64;              // per-warp P tile
    const int nit = 2 * qt + 2;

    for (int it = 0; it < nit; it++) {
        __syncthreads();
        if (it + 1 < nit) stage_kv(it + 1, (it + 1) & 1);
        CP_COMMIT;
        CP_WAIT1;
        __syncthreads();

        const int ks = it * 64;
        if (ks > qs + r0 + 15) continue;        // warp fully masked

        const float* K = smK + (it & 1) * KW;
        const float* V = smV + (it & 1) * VW;

        float S[8][4];
        #pragma unroll
        for (int nt = 0; nt < 8; nt++)
            #pragma unroll
            for (int c = 0; c < 4; c++) S[nt][c] = 0.0f;

        #pragma unroll
        for (int sc = 0; sc < 8; sc++) {
            uint4 lo = *(const uint4*)(smQ + swzq(r0 + g,     sc * 4 + q));
            uint4 hi = *(const uint4*)(smQ + swzq(r0 + g + 8, sc * 4 + q));
            #pragma unroll
            for (int nt = 0; nt < 8; nt++) {
                uint4 bv = *(const uint4*)(K + swzq(nt * 8 + g, sc * 4 + q));
                mma_tf32(S[nt], lo.x, hi.x, lo.y, hi.y, bv.x, bv.y);
                mma_tf32(S[nt], lo.z, hi.z, lo.w, hi.w, bv.z, bv.w);
            }
        }

        if (ks + 63 > qs + r0) {                // diagonal band: mask
            #pragma unroll
            for (int nt = 0; nt < 8; nt++) {
                int j = ks + nt * 8 + 2 * q;
                int ra = qs + r0 + g, rb = ra + 8;
                if (j     > ra) S[nt][0] = -1e30f;
                if (j + 1 > ra) S[nt][1] = -1e30f;
                if (j     > rb) S[nt][2] = -1e30f;
                if (j + 1 > rb) S[nt][3] = -1e30f;
            }
        }

        float mta = -1e30f, mtb = -1e30f;
        #pragma unroll
        for (int nt = 0; nt < 8; nt++) {
            mta = fmaxf(mta, fmaxf(S[nt][0], S[nt][1]));
            mtb = fmaxf(mtb, fmaxf(S[nt][2], S[nt][3]));
        }
        mta = fmaxf(mta, __shfl_xor_sync(~0u, mta, 1));
        mta = fmaxf(mta, __shfl_xor_sync(~0u, mta, 2));
        mtb = fmaxf(mtb, __shfl_xor_sync(~0u, mtb, 1));
        mtb = fmaxf(mtb, __shfl_xor_sync(~0u, mtb, 2));

        float mna = fmaxf(m_a, mta), mnb = fmaxf(m_b, mtb);
        float aa = __expf(m_a - mna), ab = __expf(m_b - mnb);
        m_a = mna; m_b = mnb;

        float rsa = 0.0f, rsb = 0.0f;
        #pragma unroll
        for (int nt = 0; nt < 8; nt++) {
            S[nt][0] = rna(__expf(S[nt][0] - mna));
            S[nt][1] = rna(__expf(S[nt][1] - mna));
            S[nt][2] = rna(__expf(S[nt][2] - mnb));
            S[nt][3] = rna(__expf(S[nt][3] - mnb));
            rsa += S[nt][0] + S[nt][1];
            rsb += S[nt][2] + S[nt][3];
        }
        rsa += __shfl_xor_sync(~0u, rsa, 1);
        rsa += __shfl_xor_sync(~0u, rsa, 2);
        rsb += __shfl_xor_sync(~0u, rsb, 1);
        rsb += __shfl_xor_sync(~0u, rsb, 2);
        l_a = l_a * aa + rsa;
        l_b = l_b * ab + rsb;

        #pragma unroll
        for (int dt = 0; dt < 16; dt++) {
            O[dt][0] *= aa; O[dt][1] *= aa;
            O[dt][2] *= ab; O[dt][3] *= ab;
        }

        // P -> per-warp smem (swizzled like VT rows)
        #pragma unroll
        for (int nt = 0; nt < 8; nt++) {
            int j = nt * 8 + 2 * q;
            uint32_t off = (uint32_t)(((j >> 2) ^ ((g & 1) << 2)) << 2) + (j & 3);
            *(float2*)&wp[(g << 6)       + off] = make_float2(S[nt][0], S[nt][1]);
            uint32_t off2 = (uint32_t)(((j >> 2) ^ (((g + 8) & 1) << 2)) << 2) + (j & 3);
            *(float2*)&wp[((g + 8) << 6) + off2] = make_float2(S[nt][2], S[nt][3]);
        }
        __syncwarp();

        // O += P V   (A = P from wp, B = VT rows d)
        #pragma unroll
        for (int jc = 0; jc < 4; jc++) {
            uint4 lo = *(const uint4*)(wp + swzv(g,     jc * 4 + q));
            uint4 hi = *(const uint4*)(wp + swzv(g + 8, jc * 4 + q));
            #pragma unroll
            for (int dt = 0; dt < 16; dt++) {
                uint4 bv = *(const uint4*)(V + swzv(dt * 8 + g, jc * 4 + q));
                mma_tf32(O[dt], lo.x, hi.x, lo.y, hi.y, bv.x, bv.y);
                mma_tf32(O[dt], lo.z, hi.z, lo.w, hi.w, bv.z, bv.w);
            }
        }
        __syncwarp();
    }

    // epilogue: normalize, rna, write [b][s][h*128+d]
    const int b = bh >> 4, h = bh & 15;
    const float inv_a = 1.0f / l_a, inv_b = 1.0f / l_b;
    const int ra = qs + r0 + g, rb = ra + 8;
    float* da = Og + ((size_t)(b * NS + ra)) * NHDIM + h * ND;
    float* db = Og + ((size_t)(b * NS + rb)) * NHDIM + h * ND;
    #pragma unroll
    for (int dt = 0; dt < 16; dt++) {
        int d = dt * 8 + 2 * q;
        *(float2*)(da + d) = make_float2(rna(O[dt][0] * inv_a), rna(O[dt][1] * inv_a));
        *(float2*)(db + d) = make_float2(rna(O[dt][2] * inv_b), rna(O[dt][3] * inv_b));
    }
}

// ==================================================================== launch
extern "C" void kernel_launch(void* const* d_in, const int* in_sizes, int n_in,
                              void* d_out, int out_size)
{
    (void)in_sizes; (void)n_in; (void)out_size;
    const float* x      = (const float*)d_in[0];
    const float* w_q    = (const float*)d_in[1];
    const float* w_k    = (const float*)d_in[2];
    const float* w_v    = (const float*)d_in[3];
    const float* w_proj = (const float*)d_in[4];
    const float* b_proj = (const float*)d_in[5];
    float* out = (float*)d_out;

    cudaFuncSetAttribute(gemm_tc, cudaFuncAttributeMaxDynamicSharedMemorySize, GSMEM);
    cudaFuncSetAttribute(fattn_tc, cudaFuncAttributeMaxDynamicSharedMemorySize, FA2_SMEM);

    float* base = nullptr;
    cudaGetSymbolAddress((void**)&base, g_scratch);
    float* xr = base + 4ll * CH;
    float* wr = base + 5ll * CH;

    round_tf32<<<(CH/4 + 255)/256, 256>>>(x, xr, CH/4);
    round_tf32<<<(WN/4 + 255)/256, 256>>>(w_q,    wr,          WN/4);
    round_tf32<<<(WN/4 + 255)/256, 256>>>(w_k,    wr + WN,     WN/4);
    round_tf32<<<(WN/4 + 255)/256, 256>>>(w_v,    wr + 2ll*WN, WN/4);
    round_tf32<<<(WN/4 + 255)/256, 256>>>(w_proj, wr + 3ll*WN, WN/4);

    dim3 blk(256);
    gemm_tc<<<dim3(48, 64), blk, GSMEM>>>(xr, wr, wr + WN, wr + 2ll*WN,
                                          nullptr, nullptr, 1);
    fattn_tc<<<dim3(NS / 128, NB * NH), blk, FA2_SMEM>>>();
    gemm_tc<<<dim3(16, 64), blk, GSMEM>>>(base + 3ll*CH, wr + 3ll*WN, nullptr,
                                          nullptr, b_proj, out, 0);
}

// round 5
// speedup vs baseline: 6.9633x; 2.1679x over previous
#include <cuda_runtime.h>
#include <cuda_fp16.h>
#include <cstdint>

#define NB 4
#define NS 2048
#define NE 2048
#define NH 16
#define ND 128
#define NHDIM 2048
#define CH (NB*NS*NHDIM)        // 16777216
#define WN (NHDIM*NE)           // 4194304
#define QK_SCALE 0.08838834764831845f

// half planes: 0 q~(scaled) 1 k~ 2 vT[bh][d][s] 3 attn_out[b][s][hd] 4 x16,
// then w16: q,k,v,proj
__device__ __half g_h[5ll*CH + 4ll*WN];

// -------------------------------------------------------------- helpers
__device__ __forceinline__ uint32_t f22h(float a, float b) {
    __half2 h = __floats2half2_rn(a, b);
    return *(uint32_t*)&h;
}
__device__ __forceinline__ void mma_f16(float* d,
    uint32_t a0, uint32_t a1, uint32_t a2, uint32_t a3, uint32_t b0, uint32_t b1)
{
    asm volatile(
        "mma.sync.aligned.m16n8k16.row.col.f32.f16.f16.f32 "
        "{%0,%1,%2,%3}, {%4,%5,%6,%7}, {%8,%9}, {%0,%1,%2,%3};\n"
        : "+f"(d[0]), "+f"(d[1]), "+f"(d[2]), "+f"(d[3])
        : "r"(a0), "r"(a1), "r"(a2), "r"(a3), "r"(b0), "r"(b1));
}
__device__ __forceinline__ void ldsm4(uint32_t& r0, uint32_t& r1,
                                      uint32_t& r2, uint32_t& r3, uint32_t addr)
{
    asm volatile("ldmatrix.sync.aligned.m8n8.x4.shared.b16 {%0,%1,%2,%3}, [%4];"
                 : "=r"(r0), "=r"(r1), "=r"(r2), "=r"(r3) : "r"(addr));
}
__device__ __forceinline__ void cpa16(uint32_t dst, const void* src) {
    asm volatile("cp.async.cg.shared.global [%0], [%1], 16;\n"
                 :: "r"(dst), "l"(src) : "memory");
}
#define CP_COMMIT asm volatile("cp.async.commit_group;\n" ::: "memory")
#define CP_WAIT1  asm volatile("cp.async.wait_group 1;\n" ::: "memory")

__global__ void to_half(const float* __restrict__ src,
                        __half* __restrict__ dst, int n4)
{
    int i = blockIdx.x * blockDim.x + threadIdx.x;
    if (i < n4) {
        float4 v = ((const float4*)src)[i];
        ((__half2*)dst)[2*i]   = __floats2half2_rn(v.x, v.y);
        ((__half2*)dst)[2*i+1] = __floats2half2_rn(v.z, v.w);
    }
}

// ================================================= fp16 tensor-core GEMM (NT)
// C[m,n] = sum_k A[m,k]*W[n,k]. Tiles 128x128x64, 3-stage cp.async, ldmatrix.
#define GTILEH 8192             // halves per tile (128 x 64)
#define GSTAGEH (2*GTILEH)
#define GSMEM (3*GSTAGEH*2)     // 98304 B

__global__ __launch_bounds__(256)
void gemm_h(const __half* __restrict__ A0, const __half* __restrict__ W0,
            const __half* __restrict__ W1, const __half* __restrict__ W2,
            const float* __restrict__ bias, float* __restrict__ Cext, int mode)
{
    extern __shared__ __half sh[];
    const int tid = threadIdx.x, lane = tid & 31, warp = tid >> 5;
    const int wm = warp >> 2, wn = warp & 3;
    const int lr = lane & 15, lc = lane >> 4;

    int bx = blockIdx.x;
    const __half* A = A0;
    const __half* W = W0;
    int wsel = -1;
    if (mode == 1) {
        wsel = bx >> 4; bx &= 15;
        W = (wsel == 0) ? W0 : (wsel == 1 ? W1 : W2);
    }
    const int m0 = blockIdx.y * 128, n0 = bx * 128;
    const __half* Ag = A + (size_t)m0 * NE;
    const __half* Wg = W + (size_t)n0 * NE;
    const uint32_t sb = (uint32_t)__cvta_generic_to_shared(sh);

    auto stage = [&](int st, int it) {
        const int k0 = it * 64;
        uint32_t ab = sb + (uint32_t)(st * GSTAGEH) * 2u;
        uint32_t bb = ab + GTILEH * 2u;
        #pragma unroll
        for (int p = 0; p < 4; p++) {
            int idx = p * 256 + tid, m = idx >> 3, c = idx & 7;
            uint32_t soff = (uint32_t)(m * 128 + ((c ^ (m & 7)) << 4));
            cpa16(ab + soff, Ag + (size_t)m * NE + k0 + c * 8);
            cpa16(bb + soff, Wg + (size_t)m * NE + k0 + c * 8);
        }
    };

    float Cc[4][4][4];
    #pragma unroll
    for (int mt = 0; mt < 4; mt++)
        #pragma unroll
        for (int nt = 0; nt < 4; nt++)
            #pragma unroll
            for (int q = 0; q < 4; q++) Cc[mt][nt][q] = 0.0f;

    stage(0, 0); CP_COMMIT;
    stage(1, 1); CP_COMMIT;

    const int NIT = NE / 64;                 // 32
    for (int it = 0; it < NIT; it++) {
        CP_WAIT1;
        __syncthreads();
        if (it + 2 < NIT) stage((it + 2) % 3, it + 2);
        CP_COMMIT;
        uint32_t ab = sb + (uint32_t)((it % 3) * GSTAGEH) * 2u;
        uint32_t bb = ab + GTILEH * 2u;

        #pragma unroll
        for (int kc = 0; kc < 4; kc++) {
            uint32_t a[4][4], b[2][4];
            #pragma unroll
            for (int mt = 0; mt < 4; mt++) {
                int row = wm * 64 + mt * 16 + lr;
                int ch  = kc * 2 + lc;
                ldsm4(a[mt][0], a[mt][1], a[mt][2], a[mt][3],
                      ab + (uint32_t)(row * 128 + ((ch ^ (row & 7)) << 4)));
            }
            #pragma unroll
            for (int nb = 0; nb < 2; nb++) {
                int row = wn * 32 + nb * 16 + lr;
                int ch  = kc * 2 + lc;
                ldsm4(b[nb][0], b[nb][1], b[nb][2], b[nb][3],
                      bb + (uint32_t)(row * 128 + ((ch ^ (row & 7)) << 4)));
            }
            #pragma unroll
            for (int mt = 0; mt < 4; mt++)
                #pragma unroll
                for (int nt = 0; nt < 4; nt++)
                    mma_f16(Cc[mt][nt], a[mt][0], a[mt][1], a[mt][2], a[mt][3],
                            b[nt >> 1][nt & 1], b[nt >> 1][(nt & 1) + 2]);
        }
    }

    // ------------------------------------------------------------ epilogue
    if (mode == 1) {
        const int h = n0 >> 7;
        if (wsel <= 1) {     // q~ (scaled) / k~ planes, fp16, [bh][s][d]
            __half* plane = g_h + (size_t)wsel * CH;
            const float mul = (wsel == 0) ? QK_SCALE : 1.0f;
            #pragma unroll
            for (int mt = 0; mt < 4; mt++)
                #pragma unroll
                for (int half = 0; half < 2; half++) {
                    int r = m0 + wm * 64 + mt * 16 + (lane >> 2) + half * 8;
                    int bb2 = r >> 11, s = r & (NS - 1);
                    __half* dst = plane + (((size_t)(bb2 * NH + h)) * NS + s) * ND;
                    #pragma unroll
                    for (int nt = 0; nt < 4; nt++) {
                        int d = wn * 32 + nt * 8 + ((lane & 3) << 1);
                        float2 v = half ? make_float2(Cc[mt][nt][2], Cc[mt][nt][3])
                                        : make_float2(Cc[mt][nt][0], Cc[mt][nt][1]);
                        *(__half2*)(dst + d) = __floats2half2_rn(v.x * mul, v.y * mul);
                    }
                }
        } else {             // V: transpose via smem -> vT[bh][d][s], fp16
            float* tr = (float*)sh;          // 128 x 132 fp32 = 67584 B
            __syncthreads();
            #pragma unroll
            for (int mt = 0; mt < 4; mt++)
                #pragma unroll
                for (int half = 0; half < 2; half++) {
                    int rl = wm * 64 + mt * 16 + (lane >> 2) + half * 8;
                    #pragma unroll
                    for (int nt = 0; nt < 4; nt++) {
                        int col = wn * 32 + nt * 8 + ((lane & 3) << 1);
                        float2 v = half ? make_float2(Cc[mt][nt][2], Cc[mt][nt][3])
                                        : make_float2(Cc[mt][nt][0], Cc[mt][nt][1]);
                        *(float2*)&tr[rl * 132 + col] = v;
                    }
                }
            __syncthreads();
            const int d = tid >> 1, s0 = (tid & 1) << 6;
            const int bb2 = m0 >> 11, sbase = m0 & (NS - 1);
            __half* dst = g_h + 2ll * CH
                        + ((size_t)((bb2 * NH + h) * ND + d)) * NS + sbase + s0;
            #pragma unroll
            for (int i = 0; i < 64; i += 2)
                *(__half2*)(dst + i) = __floats2half2_rn(tr[(s0 + i) * 132 + d],
                                                         tr[(s0 + i + 1) * 132 + d]);
        }
    } else {
        #pragma unroll
        for (int mt = 0; mt < 4; mt++)
            #pragma unroll
            for (int half = 0; half < 2; half++) {
                int r = m0 + wm * 64 + mt * 16 + (lane >> 2) + half * 8;
                float* dst = Cext + (size_t)r * NE;
                #pragma unroll
                for (int nt = 0; nt < 4; nt++) {
                    int col = n0 + wn * 32 + nt * 8 + ((lane & 3) << 1);
                    float2 v = half ? make_float2(Cc[mt][nt][2], Cc[mt][nt][3])
                                    : make_float2(Cc[mt][nt][0], Cc[mt][nt][1]);
                    v.x += bias[col]; v.y += bias[col + 1];
                    *(float2*)(dst + col) = v;
                }
            }
    }
}

// ====================================== fp16 tensor-core flash attention
// Br=128 (8 warps x 16 rows), Bc=64; Q resident; K/VT double-buffered; P in regs.
#define QHW 16384               // halves: 128 x 128
#define KHW 8192                // 64 x 128
#define VHW 8192                // 128 x 64
#define FA_SMEM ((QHW + 2*KHW + 2*VHW) * 2)   // 98304 B

__global__ __launch_bounds__(256)
void fattn_h()
{
    extern __shared__ __half fs[];
    const int tid = threadIdx.x, lane = tid & 31, w = tid >> 5;
    const int g = lane >> 2, q = lane & 3, r0 = w * 16;
    const int lr = lane & 15, lc = lane >> 4;
    const int qt = (int)gridDim.x - 1 - (int)blockIdx.x;   // heavy first
    const int qs = qt * 128;
    const int bh = blockIdx.y;

    const __half* Qg = g_h + (size_t)bh * NS * ND + (size_t)qs * ND;
    const __half* Kg = g_h + (size_t)CH + (size_t)bh * NS * ND;
    const __half* Vg = g_h + 2ll * CH + (size_t)bh * ND * NS;
    __half*       Og = g_h + 3ll * CH;
    const uint32_t sb = (uint32_t)__cvta_generic_to_shared(fs);
    const uint32_t Kb = QHW * 2u, Vb = (QHW + 2 * KHW) * 2u;

    auto stage_kv = [&](int it, int buf) {
        const int ks = it * 64;
        #pragma unroll
        for (int p = 0; p < 4; p++) {        // K: 64 rows x 16 chunks
            int idx = p * 256 + tid, m = idx >> 4, c = idx & 15;
            cpa16(sb + Kb + (uint32_t)(buf * KHW * 2 + m * 256 + ((c ^ (m & 7)) << 4)),
                  Kg + (size_t)(ks + m) * ND + c * 8);
        }
        #pragma unroll
        for (int p = 0; p < 4; p++) {        // VT: 128 d-rows x 8 chunks
            int idx = p * 256 + tid, d = idx >> 3, c = idx & 7;
            cpa16(sb + Vb + (uint32_t)(buf * VHW * 2 + d * 128 + ((c ^ (d & 7)) << 4)),
                  Vg + (size_t)d * NS + ks + c * 8);
        }
    };

    #pragma unroll
    for (int p = 0; p < 8; p++) {            // Q once: 128 rows x 16 chunks
        int idx = p * 256 + tid, m = idx >> 4, c = idx & 15;
        cpa16(sb + (uint32_t)(m * 256 + ((c ^ (m & 7)) << 4)),
              Qg + (size_t)m * ND + c * 8);
    }
    CP_COMMIT;
    stage_kv(0, 0); CP_COMMIT;

    float m_a = -1e30f, m_b = -1e30f, l_a = 0.0f, l_b = 0.0f;
    float O[16][4];
    #pragma unroll
    for (int dt = 0; dt < 16; dt++)
        #pragma unroll
        for (int c = 0; c < 4; c++) O[dt][c] = 0.0f;

    const int nit = 2 * qt + 2;
    for (int it = 0; it < nit; it++) {
        __syncthreads();
        if (it + 1 < nit) stage_kv(it + 1, (it + 1) & 1);
        CP_COMMIT;
        CP_WAIT1;
        __syncthreads();

        const int ks = it * 64;
        if (ks > qs + r0 + 15) continue;     // warp fully masked

        const uint32_t Kbb = sb + Kb + (uint32_t)((it & 1) * KHW * 2);
        const uint32_t Vbb = sb + Vb + (uint32_t)((it & 1) * VHW * 2);

        float S[8][4];
        #pragma unroll
        for (int nt = 0; nt < 8; nt++)
            #pragma unroll
            for (int c = 0; c < 4; c++) S[nt][c] = 0.0f;

        #pragma unroll
        for (int kc = 0; kc < 8; kc++) {     // d chunks of 16
            uint32_t aq0, aq1, aq2, aq3;
            {
                int row = r0 + lr, ch = kc * 2 + lc;
                ldsm4(aq0, aq1, aq2, aq3,
                      sb + (uint32_t)(row * 256 + ((ch ^ (row & 7)) << 4)));
            }
            #pragma unroll
            for (int b2 = 0; b2 < 4; b2++) {
                uint32_t bk0, bk1, bk2, bk3;
                int row = b2 * 16 + lr, ch = kc * 2 + lc;
                ldsm4(bk0, bk1, bk2, bk3,
                      Kbb + (uint32_t)(row * 256 + ((ch ^ (row & 7)) << 4)));
                mma_f16(S[2*b2],   aq0, aq1, aq2, aq3, bk0, bk2);
                mma_f16(S[2*b2+1], aq0, aq1, aq2, aq3, bk1, bk3);
            }
        }

        if (ks + 63 > qs + r0) {             // diagonal band: causal mask
            #pragma unroll
            for (int nt = 0; nt < 8; nt++) {
                int j = ks + nt * 8 + 2 * q;
                int ra = qs + r0 + g, rb = ra + 8;
                if (j     > ra) S[nt][0] = -1e30f;
                if (j + 1 > ra) S[nt][1] = -1e30f;
                if (j     > rb) S[nt][2] = -1e30f;
                if (j + 1 > rb) S[nt][3] = -1e30f;
            }
        }

        float mta = -1e30f, mtb = -1e30f;
        #pragma unroll
        for (int nt = 0; nt < 8; nt++) {
            mta = fmaxf(mta, fmaxf(S[nt][0], S[nt][1]));
            mtb = fmaxf(mtb, fmaxf(S[nt][2], S[nt][3]));
        }
        mta = fmaxf(mta, __shfl_xor_sync(~0u, mta, 1));
        mta = fmaxf(mta, __shfl_xor_sync(~0u, mta, 2));
        mtb = fmaxf(mtb, __shfl_xor_sync(~0u, mtb, 1));
        mtb = fmaxf(mtb, __shfl_xor_sync(~0u, mtb, 2));

        float mna = fmaxf(m_a, mta), mnb = fmaxf(m_b, mtb);
        float aa = __expf(m_a - mna), ab = __expf(m_b - mnb);
        m_a = mna; m_b = mnb;

        float rsa = 0.0f, rsb = 0.0f;
        #pragma unroll
        for (int nt = 0; nt < 8; nt++) {
            S[nt][0] = __expf(S[nt][0] - mna);
            S[nt][1] = __expf(S[nt][1] - mna);
            S[nt][2] = __expf(S[nt][2] - mnb);
            S[nt][3] = __expf(S[nt][3] - mnb);
            rsa += S[nt][0] + S[nt][1];
            rsb += S[nt][2] + S[nt][3];
        }
        rsa += __shfl_xor_sync(~0u, rsa, 1);
        rsa += __shfl_xor_sync(~0u, rsa, 2);
        rsb += __shfl_xor_sync(~0u, rsb, 1);
        rsb += __shfl_xor_sync(~0u, rsb, 2);
        l_a = l_a * aa + rsa;
        l_b = l_b * ab + rsb;

        #pragma unroll
        for (int dt = 0; dt < 16; dt++) {
            O[dt][0] *= aa; O[dt][1] *= aa;
            O[dt][2] *= ab; O[dt][3] *= ab;
        }

        // P: registers -> fp16 A-fragments (C layout == A layout), no smem
        uint32_t pa[4][4];
        #pragma unroll
        for (int k2 = 0; k2 < 4; k2++) {
            pa[k2][0] = f22h(S[2*k2][0],   S[2*k2][1]);
            pa[k2][1] = f22h(S[2*k2][2],   S[2*k2][3]);
            pa[k2][2] = f22h(S[2*k2+1][0], S[2*k2+1][1]);
            pa[k2][3] = f22h(S[2*k2+1][2], S[2*k2+1][3]);
        }

        // O += P V  (B from VT[d][key], rows = d)
        #pragma unroll
        for (int k2 = 0; k2 < 4; k2++) {     // key chunks of 16
            #pragma unroll
            for (int b2 = 0; b2 < 8; b2++) { // d blocks of 16
                uint32_t bv0, bv1, bv2, bv3;
                int row = b2 * 16 + lr, ch = k2 * 2 + lc;
                ldsm4(bv0, bv1, bv2, bv3,
                      Vbb + (uint32_t)(row * 128 + ((ch ^ (row & 7)) << 4)));
                mma_f16(O[2*b2],   pa[k2][0], pa[k2][1], pa[k2][2], pa[k2][3], bv0, bv2);
                mma_f16(O[2*b2+1], pa[k2][0], pa[k2][1], pa[k2][2], pa[k2][3], bv1, bv3);
            }
        }
    }

    // epilogue: normalize, write fp16 attn_out [b][s][h*128+d]
    const int b = bh >> 4, h = bh & 15;
    const float inv_a = 1.0f / l_a, inv_b = 1.0f / l_b;
    const int ra = qs + r0 + g, rb = ra + 8;
    __half* da = Og + ((size_t)(b * NS + ra)) * NHDIM + h * ND;
    __half* db = Og + ((size_t)(b * NS + rb)) * NHDIM + h * ND;
    #pragma unroll
    for (int dt = 0; dt < 16; dt++) {
        int d = dt * 8 + 2 * q;
        *(__half2*)(da + d) = __floats2half2_rn(O[dt][0] * inv_a, O[dt][1] * inv_a);
        *(__half2*)(db + d) = __floats2half2_rn(O[dt][2] * inv_b, O[dt][3] * inv_b);
    }
}

// ==================================================================== launch
extern "C" void kernel_launch(void* const* d_in, const int* in_sizes, int n_in,
                              void* d_out, int out_size)
{
    (void)in_sizes; (void)n_in; (void)out_size;
    const float* x      = (const float*)d_in[0];
    const float* w_q    = (const float*)d_in[1];
    const float* w_k    = (const float*)d_in[2];
    const float* w_v    = (const float*)d_in[3];
    const float* w_proj = (const float*)d_in[4];
    const float* b_proj = (const float*)d_in[5];
    float* out = (float*)d_out;

    cudaFuncSetAttribute(gemm_h, cudaFuncAttributeMaxDynamicSharedMemorySize, GSMEM);
    cudaFuncSetAttribute(fattn_h, cudaFuncAttributeMaxDynamicSharedMemorySize, FA_SMEM);

    __half* base = nullptr;
    cudaGetSymbolAddress((void**)&base, g_h);
    __half* hx = base + 4ll * CH;
    __half* hw = base + 5ll * CH;

    to_half<<<(CH/4 + 255)/256, 256>>>(x, hx, CH/4);
    to_half<<<(WN/4 + 255)/256, 256>>>(w_q,    hw,          WN/4);
    to_half<<<(WN/4 + 255)/256, 256>>>(w_k,    hw + WN,     WN/4);
    to_half<<<(WN/4 + 255)/256, 256>>>(w_v,    hw + 2ll*WN, WN/4);
    to_half<<<(WN/4 + 255)/256, 256>>>(w_proj, hw + 3ll*WN, WN/4);

    dim3 blk(256);
    gemm_h<<<dim3(48, 64), blk, GSMEM>>>(hx, hw, hw + WN, hw + 2ll*WN,
                                         nullptr, nullptr, 1);
    fattn_h<<<dim3(NS / 128, NB * NH), blk, FA_SMEM>>>();
    gemm_h<<<dim3(16, 64), blk, GSMEM>>>(base + 3ll*CH, hw + 3ll*WN, nullptr,
                                         nullptr, b_proj, out, 0);
}

// round 7
// speedup vs baseline: 7.1323x; 1.0243x over previous
#include <cuda_runtime.h>
#include <cuda_fp16.h>
#include <cstdint>

#define NB 4
#define NS 2048
#define NE 2048
#define NH 16
#define ND 128
#define NHDIM 2048
#define CH (NB*NS*NHDIM)        // 16777216
#define WN (NHDIM*NE)           // 4194304 (CH == 4*WN)
#define QK_SCALE 0.08838834764831845f

// half planes: 0 q~(scaled) 1 k~ 2 vT[bh][d][s] 3 attn_out[b][s][hd] 4 x16,
// then w16: q,k,v,proj
__device__ __half g_h[5ll*CH + 4ll*WN];

// -------------------------------------------------------------- helpers
__device__ __forceinline__ uint32_t f22h(float a, float b) {
    __half2 h = __floats2half2_rn(a, b);
    return *(uint32_t*)&h;
}
__device__ __forceinline__ void mma_f16(float* d,
    uint32_t a0, uint32_t a1, uint32_t a2, uint32_t a3, uint32_t b0, uint32_t b1)
{
    asm volatile(
        "mma.sync.aligned.m16n8k16.row.col.f32.f16.f16.f32 "
        "{%0,%1,%2,%3}, {%4,%5,%6,%7}, {%8,%9}, {%0,%1,%2,%3};\n"
        : "+f"(d[0]), "+f"(d[1]), "+f"(d[2]), "+f"(d[3])
        : "r"(a0), "r"(a1), "r"(a2), "r"(a3), "r"(b0), "r"(b1));
}
__device__ __forceinline__ void ldsm4(uint32_t& r0, uint32_t& r1,
                                      uint32_t& r2, uint32_t& r3, uint32_t addr)
{
    asm volatile("ldmatrix.sync.aligned.m8n8.x4.shared.b16 {%0,%1,%2,%3}, [%4];"
                 : "=r"(r0), "=r"(r1), "=r"(r2), "=r"(r3) : "r"(addr));
}
__device__ __forceinline__ void cpa16(uint32_t dst, const void* src) {
    asm volatile("cp.async.cg.shared.global [%0], [%1], 16;\n"
                 :: "r"(dst), "l"(src) : "memory");
}
#define CP_COMMIT asm volatile("cp.async.commit_group;\n" ::: "memory")
#define CP_WAIT1  asm volatile("cp.async.wait_group 1;\n" ::: "memory")

// fused fp32->fp16 conversion: 8 segments of WN elements each.
// segs 0-3: x (contiguous), segs 4-7: w_q, w_k, w_v, w_proj.
__global__ void to_half_all(const float* __restrict__ x,
                            const float* __restrict__ wq,
                            const float* __restrict__ wk,
                            const float* __restrict__ wv,
                            const float* __restrict__ wp,
                            __half* __restrict__ dst)
{
    const int seg = blockIdx.y;
    const float* src;
    if (seg < 4)       src = x + (size_t)seg * WN;
    else if (seg == 4) src = wq;
    else if (seg == 5) src = wk;
    else if (seg == 6) src = wv;
    else               src = wp;
    __half* d = dst + (size_t)seg * WN;

    int i = blockIdx.x * blockDim.x + threadIdx.x;   // float4 index, WN/4 per seg
    float4 v = ((const float4*)src)[i];
    ((__half2*)d)[2*i]   = __floats2half2_rn(v.x, v.y);
    ((__half2*)d)[2*i+1] = __floats2half2_rn(v.z, v.w);
}

// ================================================= fp16 tensor-core GEMM (NT)
// C[m,n] = sum_k A[m,k]*W[n,k]. Tiles 128x128x64, 3-stage cp.async, ldmatrix.
#define GTILEH 8192             // halves per tile (128 x 64)
#define GSTAGEH (2*GTILEH)
#define GSMEM (3*GSTAGEH*2)     // 98304 B

__global__ __launch_bounds__(256, 2)
void gemm_h(const __half* __restrict__ A0, const __half* __restrict__ W0,
            const __half* __restrict__ W1, const __half* __restrict__ W2,
            const float* __restrict__ bias, float* __restrict__ Cext, int mode)
{
    extern __shared__ __half sh[];
    const int tid = threadIdx.x, lane = tid & 31, warp = tid >> 5;
    const int wm = warp >> 2, wn = warp & 3;
    const int lr = lane & 15, lc = lane >> 4;

    int bx = blockIdx.x;
    const __half* A = A0;
    const __half* W = W0;
    int wsel = -1;
    if (mode == 1) {
        wsel = bx >> 4; bx &= 15;
        W = (wsel == 0) ? W0 : (wsel == 1 ? W1 : W2);
    }
    const int m0 = blockIdx.y * 128, n0 = bx * 128;
    const __half* Ag = A + (size_t)m0 * NE;
    const __half* Wg = W + (size_t)n0 * NE;
    const uint32_t sb = (uint32_t)__cvta_generic_to_shared(sh);

    auto stage = [&](int st, int it) {
        const int k0 = it * 64;
        uint32_t ab = sb + (uint32_t)(st * GSTAGEH) * 2u;
        uint32_t bb = ab + GTILEH * 2u;
        #pragma unroll
        for (int p = 0; p < 4; p++) {
            int idx = p * 256 + tid, m = idx >> 3, c = idx & 7;
            uint32_t soff = (uint32_t)(m * 128 + ((c ^ (m & 7)) << 4));
            cpa16(ab + soff, Ag + (size_t)m * NE + k0 + c * 8);
            cpa16(bb + soff, Wg + (size_t)m * NE + k0 + c * 8);
        }
    };

    float Cc[4][4][4];
    #pragma unroll
    for (int mt = 0; mt < 4; mt++)
        #pragma unroll
        for (int nt = 0; nt < 4; nt++)
            #pragma unroll
            for (int q = 0; q < 4; q++) Cc[mt][nt][q] = 0.0f;

    stage(0, 0); CP_COMMIT;
    stage(1, 1); CP_COMMIT;

    const int NIT = NE / 64;                 // 32
    for (int it = 0; it < NIT; it++) {
        CP_WAIT1;
        __syncthreads();
        if (it + 2 < NIT) stage((it + 2) % 3, it + 2);
        CP_COMMIT;
        uint32_t ab = sb + (uint32_t)((it % 3) * GSTAGEH) * 2u;
        uint32_t bb = ab + GTILEH * 2u;

        #pragma unroll
        for (int kc = 0; kc < 4; kc++) {
            uint32_t a[4][4], b[2][4];
            #pragma unroll
            for (int mt = 0; mt < 4; mt++) {
                int row = wm * 64 + mt * 16 + lr;
                int ch  = kc * 2 + lc;
                ldsm4(a[mt][0], a[mt][1], a[mt][2], a[mt][3],
                      ab + (uint32_t)(row * 128 + ((ch ^ (row & 7)) << 4)));
            }
            #pragma unroll
            for (int nb = 0; nb < 2; nb++) {
                int row = wn * 32 + nb * 16 + lr;
                int ch  = kc * 2 + lc;
                ldsm4(b[nb][0], b[nb][1], b[nb][2], b[nb][3],
                      bb + (uint32_t)(row * 128 + ((ch ^ (row & 7)) << 4)));
            }
            #pragma unroll
            for (int mt = 0; mt < 4; mt++)
                #pragma unroll
                for (int nt = 0; nt < 4; nt++)
                    mma_f16(Cc[mt][nt], a[mt][0], a[mt][1], a[mt][2], a[mt][3],
                            b[nt >> 1][nt & 1], b[nt >> 1][(nt & 1) + 2]);
        }
    }

    // ------------------------------------------------------------ epilogue
    if (mode == 1) {
        const int h = n0 >> 7;
        if (wsel <= 1) {     // q~ (scaled) / k~ planes, fp16, [bh][s][d]
            __half* plane = g_h + (size_t)wsel * CH;
            const float mul = (wsel == 0) ? QK_SCALE : 1.0f;
            #pragma unroll
            for (int mt = 0; mt < 4; mt++)
                #pragma unroll
                for (int half = 0; half < 2; half++) {
                    int r = m0 + wm * 64 + mt * 16 + (lane >> 2) + half * 8;
                    int bb2 = r >> 11, s = r & (NS - 1);
                    __half* dst = plane + (((size_t)(bb2 * NH + h)) * NS + s) * ND;
                    #pragma unroll
                    for (int nt = 0; nt < 4; nt++) {
                        int d = wn * 32 + nt * 8 + ((lane & 3) << 1);
                        float2 v = half ? make_float2(Cc[mt][nt][2], Cc[mt][nt][3])
                                        : make_float2(Cc[mt][nt][0], Cc[mt][nt][1]);
                        *(__half2*)(dst + d) = __floats2half2_rn(v.x * mul, v.y * mul);
                    }
                }
        } else {             // V: transpose via smem -> vT[bh][d][s], fp16
            float* tr = (float*)sh;          // 128 x 132 fp32 = 67584 B
            __syncthreads();
            #pragma unroll
            for (int mt = 0; mt < 4; mt++)
                #pragma unroll
                for (int half = 0; half < 2; half++) {
                    int rl = wm * 64 + mt * 16 + (lane >> 2) + half * 8;
                    #pragma unroll
                    for (int nt = 0; nt < 4; nt++) {
                        int col = wn * 32 + nt * 8 + ((lane & 3) << 1);
                        float2 v = half ? make_float2(Cc[mt][nt][2], Cc[mt][nt][3])
                                        : make_float2(Cc[mt][nt][0], Cc[mt][nt][1]);
                        *(float2*)&tr[rl * 132 + col] = v;
                    }
                }
            __syncthreads();
            const int d = tid >> 1, s0 = (tid & 1) << 6;
            const int bb2 = m0 >> 11, sbase = m0 & (NS - 1);
            __half* dst = g_h + 2ll * CH
                        + ((size_t)((bb2 * NH + h) * ND + d)) * NS + sbase + s0;
            #pragma unroll
            for (int i = 0; i < 64; i += 2)
                *(__half2*)(dst + i) = __floats2half2_rn(tr[(s0 + i) * 132 + d],
                                                         tr[(s0 + i + 1) * 132 + d]);
        }
    } else {
        #pragma unroll
        for (int mt = 0; mt < 4; mt++)
            #pragma unroll
            for (int half = 0; half < 2; half++) {
                int r = m0 + wm * 64 + mt * 16 + (lane >> 2) + half * 8;
                float* dst = Cext + (size_t)r * NE;
                #pragma unroll
                for (int nt = 0; nt < 4; nt++) {
                    int col = n0 + wn * 32 + nt * 8 + ((lane & 3) << 1);
                    float2 v = half ? make_float2(Cc[mt][nt][2], Cc[mt][nt][3])
                                    : make_float2(Cc[mt][nt][0], Cc[mt][nt][1]);
                    v.x += bias[col]; v.y += bias[col + 1];
                    *(float2*)(dst + col) = v;
                }
            }
    }
}

// ====================================== fp16 tensor-core flash attention
// Br=128 (8 warps x 16 rows), Bc=64; Q resident; K/VT double-buffered; P in regs.
#define QHW 16384               // halves: 128 x 128
#define KHW 8192                // 64 x 128
#define VHW 8192                // 128 x 64
#define FA_SMEM ((QHW + 2*KHW + 2*VHW) * 2)   // 98304 B

__global__ __launch_bounds__(256, 2)
void fattn_h()
{
    extern __shared__ __half fs[];
    const int tid = threadIdx.x, lane = tid & 31, w = tid >> 5;
    const int g = lane >> 2, q = lane & 3, r0 = w * 16;
    const int lr = lane & 15, lc = lane >> 4;
    const int qt = (int)gridDim.x - 1 - (int)blockIdx.x;   // heavy first
    const int qs = qt * 128;
    const int bh = blockIdx.y;

    const __half* Qg = g_h + (size_t)bh * NS * ND + (size_t)qs * ND;
    const __half* Kg = g_h + (size_t)CH + (size_t)bh * NS * ND;
    const __half* Vg = g_h + 2ll * CH + (size_t)bh * ND * NS;
    __half*       Og = g_h + 3ll * CH;
    const uint32_t sb = (uint32_t)__cvta_generic_to_shared(fs);
    const uint32_t Kb = QHW * 2u, Vb = (QHW + 2 * KHW) * 2u;

    auto stage_kv = [&](int it, int buf) {
        const int ks = it * 64;
        #pragma unroll
        for (int p = 0; p < 4; p++) {        // K: 64 rows x 16 chunks
            int idx = p * 256 + tid, m = idx >> 4, c = idx & 15;
            cpa16(sb + Kb + (uint32_t)(buf * KHW * 2 + m * 256 + ((c ^ (m & 7)) << 4)),
                  Kg + (size_t)(ks + m) * ND + c * 8);
        }
        #pragma unroll
        for (int p = 0; p < 4; p++) {        // VT: 128 d-rows x 8 chunks
            int idx = p * 256 + tid, d = idx >> 3, c = idx & 7;
            cpa16(sb + Vb + (uint32_t)(buf * VHW * 2 + d * 128 + ((c ^ (d & 7)) << 4)),
                  Vg + (size_t)d * NS + ks + c * 8);
        }
    };

    #pragma unroll
    for (int p = 0; p < 8; p++) {            // Q once: 128 rows x 16 chunks
        int idx = p * 256 + tid, m = idx >> 4, c = idx & 15;
        cpa16(sb + (uint32_t)(m * 256 + ((c ^ (m & 7)) << 4)),
              Qg + (size_t)m * ND + c * 8);
    }
    CP_COMMIT;
    stage_kv(0, 0); CP_COMMIT;

    float m_a = -1e30f, m_b = -1e30f, l_a = 0.0f, l_b = 0.0f;
    float O[16][4];
    #pragma unroll
    for (int dt = 0; dt < 16; dt++)
        #pragma unroll
        for (int c = 0; c < 4; c++) O[dt][c] = 0.0f;

    const int nit = 2 * qt + 2;
    for (int it = 0; it < nit; it++) {
        __syncthreads();
        if (it + 1 < nit) stage_kv(it + 1, (it + 1) & 1);
        CP_COMMIT;
        CP_WAIT1;
        __syncthreads();

        const int ks = it * 64;
        if (ks > qs + r0 + 15) continue;     // warp fully masked

        const uint32_t Kbb = sb + Kb + (uint32_t)((it & 1) * KHW * 2);
        const uint32_t Vbb = sb + Vb + (uint32_t)((it & 1) * VHW * 2);

        float S[8][4];
        #pragma unroll
        for (int nt = 0; nt < 8; nt++)
            #pragma unroll
            for (int c = 0; c < 4; c++) S[nt][c] = 0.0f;

        #pragma unroll
        for (int kc = 0; kc < 8; kc++) {     // d chunks of 16
            uint32_t aq0, aq1, aq2, aq3;
            {
                int row = r0 + lr, ch = kc * 2 + lc;
                ldsm4(aq0, aq1, aq2, aq3,
                      sb + (uint32_t)(row * 256 + ((ch ^ (row & 7)) << 4)));
            }
            #pragma unroll
            for (int b2 = 0; b2 < 4; b2++) {
                uint32_t bk0, bk1, bk2, bk3;
                int row = b2 * 16 + lr, ch = kc * 2 + lc;
                ldsm4(bk0, bk1, bk2, bk3,
                      Kbb + (uint32_t)(row * 256 + ((ch ^ (row & 7)) << 4)));
                mma_f16(S[2*b2],   aq0, aq1, aq2, aq3, bk0, bk2);
                mma_f16(S[2*b2+1], aq0, aq1, aq2, aq3, bk1, bk3);
            }
        }

        if (ks + 63 > qs + r0) {             // diagonal band: causal mask
            #pragma unroll
            for (int nt = 0; nt < 8; nt++) {
                int j = ks + nt * 8 + 2 * q;
                int ra = qs + r0 + g, rb = ra + 8;
                if (j     > ra) S[nt][0] = -1e30f;
                if (j + 1 > ra) S[nt][1] = -1e30f;
                if (j     > rb) S[nt][2] = -1e30f;
                if (j + 1 > rb) S[nt][3] = -1e30f;
            }
        }

        float mta = -1e30f, mtb = -1e30f;
        #pragma unroll
        for (int nt = 0; nt < 8; nt++) {
            mta = fmaxf(mta, fmaxf(S[nt][0], S[nt][1]));
            mtb = fmaxf(mtb, fmaxf(S[nt][2], S[nt][3]));
        }
        mta = fmaxf(mta, __shfl_xor_sync(~0u, mta, 1));
        mta = fmaxf(mta, __shfl_xor_sync(~0u, mta, 2));
        mtb = fmaxf(mtb, __shfl_xor_sync(~0u, mtb, 1));
        mtb = fmaxf(mtb, __shfl_xor_sync(~0u, mtb, 2));

        float mna = fmaxf(m_a, mta), mnb = fmaxf(m_b, mtb);
        float aa = __expf(m_a - mna), ab = __expf(m_b - mnb);
        m_a = mna; m_b = mnb;

        float rsa = 0.0f, rsb = 0.0f;
        #pragma unroll
        for (int nt = 0; nt < 8; nt++) {
            S[nt][0] = __expf(S[nt][0] - mna);
            S[nt][1] = __expf(S[nt][1] - mna);
            S[nt][2] = __expf(S[nt][2] - mnb);
            S[nt][3] = __expf(S[nt][3] - mnb);
            rsa += S[nt][0] + S[nt][1];
            rsb += S[nt][2] + S[nt][3];
        }
        rsa += __shfl_xor_sync(~0u, rsa, 1);
        rsa += __shfl_xor_sync(~0u, rsa, 2);
        rsb += __shfl_xor_sync(~0u, rsb, 1);
        rsb += __shfl_xor_sync(~0u, rsb, 2);
        l_a = l_a * aa + rsa;
        l_b = l_b * ab + rsb;

        #pragma unroll
        for (int dt = 0; dt < 16; dt++) {
            O[dt][0] *= aa; O[dt][1] *= aa;
            O[dt][2] *= ab; O[dt][3] *= ab;
        }

        // P: registers -> fp16 A-fragments (C layout == A layout), no smem
        uint32_t pa[4][4];
        #pragma unroll
        for (int k2 = 0; k2 < 4; k2++) {
            pa[k2][0] = f22h(S[2*k2][0],   S[2*k2][1]);
            pa[k2][1] = f22h(S[2*k2][2],   S[2*k2][3]);
            pa[k2][2] = f22h(S[2*k2+1][0], S[2*k2+1][1]);
            pa[k2][3] = f22h(S[2*k2+1][2], S[2*k2+1][3]);
        }

        // O += P V  (B from VT[d][key], rows = d)
        #pragma unroll
        for (int k2 = 0; k2 < 4; k2++) {     // key chunks of 16
            #pragma unroll
            for (int b2 = 0; b2 < 8; b2++) { // d blocks of 16
                uint32_t bv0, bv1, bv2, bv3;
                int row = b2 * 16 + lr, ch = k2 * 2 + lc;
                ldsm4(bv0, bv1, bv2, bv3,
                      Vbb + (uint32_t)(row * 128 + ((ch ^ (row & 7)) << 4)));
                mma_f16(O[2*b2],   pa[k2][0], pa[k2][1], pa[k2][2], pa[k2][3], bv0, bv2);
                mma_f16(O[2*b2+1], pa[k2][0], pa[k2][1], pa[k2][2], pa[k2][3], bv1, bv3);
            }
        }
    }

    // epilogue: normalize, write fp16 attn_out [b][s][h*128+d]
    const int b = bh >> 4, h = bh & 15;
    const float inv_a = 1.0f / l_a, inv_b = 1.0f / l_b;
    const int ra = qs + r0 + g, rb = ra + 8;
    __half* da = Og + ((size_t)(b * NS + ra)) * NHDIM + h * ND;
    __half* db = Og + ((size_t)(b * NS + rb)) * NHDIM + h * ND;
    #pragma unroll
    for (int dt = 0; dt < 16; dt++) {
        int d = dt * 8 + 2 * q;
        *(__half2*)(da + d) = __floats2half2_rn(O[dt][0] * inv_a, O[dt][1] * inv_a);
        *(__half2*)(db + d) = __floats2half2_rn(O[dt][2] * inv_b, O[dt][3] * inv_b);
    }
}

// ==================================================================== launch
extern "C" void kernel_launch(void* const* d_in, const int* in_sizes, int n_in,
                              void* d_out, int out_size)
{
    (void)in_sizes; (void)n_in; (void)out_size;
    const float* x      = (const float*)d_in[0];
    const float* w_q    = (const float*)d_in[1];
    const float* w_k    = (const float*)d_in[2];
    const float* w_v    = (const float*)d_in[3];
    const float* w_proj = (const float*)d_in[4];
    const float* b_proj = (const float*)d_in[5];
    float* out = (float*)d_out;

    cudaFuncSetAttribute(gemm_h, cudaFuncAttributeMaxDynamicSharedMemorySize, GSMEM);
    cudaFuncSetAttribute(fattn_h, cudaFuncAttributeMaxDynamicSharedMemorySize, FA_SMEM);

    __half* base = nullptr;
    cudaGetSymbolAddress((void**)&base, g_h);
    __half* hx = base + 4ll * CH;
    __half* hw = base + 5ll * CH;

    // one fused conversion launch: [x | w_q | w_k | w_v | w_proj] -> fp16
    to_half_all<<<dim3(WN / 4 / 256, 8), 256>>>(x, w_q, w_k, w_v, w_proj, hx);

    dim3 blk(256);
    gemm_h<<<dim3(48, 64), blk, GSMEM>>>(hx, hw, hw + WN, hw + 2ll*WN,
                                         nullptr, nullptr, 1);
    fattn_h<<<dim3(NS / 128, NB * NH), blk, FA_SMEM>>>();
    gemm_h<<<dim3(16, 64), blk, GSMEM>>>(base + 3ll*CH, hw + 3ll*WN, nullptr,
                                         nullptr, b_proj, out, 0);
}